// round 5
// baseline (speedup 1.0000x reference)
#include <cuda_runtime.h>

#define BB 16
#define TT 2048
#define CC 288
#define CC4 (CC/4)
#define HS 32
#define NROWS (BB*TT)
#define TROWS 256         // t rows per attn block (2 per thread)
#define NTHR 128
#define TSW  128          // s-subtile staged in smem
#define SC   256          // s-chunk per block
#define NC   (TT/SC)      // 8 chunks
#define QKSCALE 0.17677669529663687f   // 32^-0.5, folded into Wk

typedef unsigned long long u64;

// ---- scratch (device globals; cudaMalloc forbidden) ----
__device__ float      g_k[NROWS*HS];             // pre-scaled by QKSCALE
__device__ float      g_q[NROWS*HS];
__device__ float      g_v[NROWS*HS];
__device__ ulonglong2 g_wq[3*CC4*HS];            // [proj][c4][h]: 4 packed w's
__device__ float      g_pacc[(size_t)NC*NROWS*HS];
__device__ float      g_pden[NC*NROWS];

// ---- packed f32x2 helpers ----
__device__ __forceinline__ u64 fma2(u64 a, u64 b, u64 c) {
    u64 d; asm("fma.rn.f32x2 %0,%1,%2,%3;" : "=l"(d) : "l"(a), "l"(b), "l"(c)); return d;
}
__device__ __forceinline__ u64 add2(u64 a, u64 b) {
    u64 d; asm("add.rn.f32x2 %0,%1,%2;" : "=l"(d) : "l"(a), "l"(b)); return d;
}
__device__ __forceinline__ u64 pack2(float lo, float hi) {
    u64 d; asm("mov.b64 %0,{%1,%2};" : "=l"(d) : "f"(lo), "f"(hi)); return d;
}
__device__ __forceinline__ float2 unpack2(u64 a) {
    float lo, hi; asm("mov.b64 {%0,%1},%2;" : "=f"(lo), "=f"(hi) : "l"(a));
    return make_float2(lo, hi);
}

// ---- (tile, chunk) work list: 8 tiles x 8 chunks, c <= tile.
// Full pairs (c < tile) first, diagonals (c == tile) last. tile | (c<<8). ----
static __device__ const int g_pairs[36] = {
    1,2,3,4,5,6,7,                      // c0 full
    258,259,260,261,262,263,            // c1 full
    515,516,517,518,519,                // c2 full
    772,773,774,775,                    // c3 full
    1029,1030,1031,                     // c4 full
    1286,1287,                          // c5 full
    1543,                               // c6 full
    0,257,514,771,1028,1285,1542,1799   // diagonals
};

// -------------------------------------------------------------------------
// Prepack: W quads, c-major per h lane -> proj W loads are coalesced LDG.128
// delivering ready-packed f32x2 operands. Wk pre-scaled by 32^-0.5.
// -------------------------------------------------------------------------
__global__ void prepack_kernel(const float* __restrict__ Wk,
                               const float* __restrict__ Wq,
                               const float* __restrict__ Wv) {
    int i = blockIdx.x * 256 + threadIdx.x;
    if (i >= 3 * CC4 * HS) return;
    int h = i & (HS - 1);
    int c4 = (i >> 5) % CC4;
    int p = i / (CC4 * HS);
    const float* W = (p == 0) ? Wk : (p == 1) ? Wq : Wv;
    float s = (p == 0) ? QKSCALE : 1.0f;
    float w0 = W[(4 * c4 + 0) * HS + h] * s;
    float w1 = W[(4 * c4 + 1) * HS + h] * s;
    float w2 = W[(4 * c4 + 2) * HS + h] * s;
    float w3 = W[(4 * c4 + 3) * HS + h] * s;
    ulonglong2 r; r.x = pack2(w0, w1); r.y = pack2(w2, w3);
    g_wq[i] = r;
}

// -------------------------------------------------------------------------
// Projection. Block (32,8): 32 rows of x in smem as u64 c-pairs. Thread
// (h, r) computes dim h of rows r, r+8, r+16, r+24 for all 3 projections.
// Per c4: 3 coalesced LDG.128 (W quads) + 4 broadcast LDS.128 (x) + 24 FMA2.
// -------------------------------------------------------------------------
#define PR 32
__global__ void proj_kernel(const float* __restrict__ x) {
    __shared__ ulonglong2 xs[PR * CC4];            // 36 KB
    int row0 = blockIdx.x * PR;
    int tid = threadIdx.y * 32 + threadIdx.x;
    const ulonglong2* xr = (const ulonglong2*)(x + (size_t)row0 * CC);
    for (int i = tid; i < PR * CC4; i += 256) xs[i] = xr[i];
    __syncthreads();

    int h = threadIdx.x, r = threadIdx.y;
    const ulonglong2* x0 = xs + (r)      * CC4;
    const ulonglong2* x1 = xs + (r + 8)  * CC4;
    const ulonglong2* x2 = xs + (r + 16) * CC4;
    const ulonglong2* x3 = xs + (r + 24) * CC4;

    u64 ak[4] = {0,0,0,0}, aq[4] = {0,0,0,0}, av[4] = {0,0,0,0};
#pragma unroll 4
    for (int c4 = 0; c4 < CC4; c4++) {
        ulonglong2 wk = g_wq[(0 * CC4 + c4) * HS + h];
        ulonglong2 wq = g_wq[(1 * CC4 + c4) * HS + h];
        ulonglong2 wv = g_wq[(2 * CC4 + c4) * HS + h];
        ulonglong2 xv;
        xv = x0[c4];
        ak[0]=fma2(xv.x,wk.x,ak[0]); ak[0]=fma2(xv.y,wk.y,ak[0]);
        aq[0]=fma2(xv.x,wq.x,aq[0]); aq[0]=fma2(xv.y,wq.y,aq[0]);
        av[0]=fma2(xv.x,wv.x,av[0]); av[0]=fma2(xv.y,wv.y,av[0]);
        xv = x1[c4];
        ak[1]=fma2(xv.x,wk.x,ak[1]); ak[1]=fma2(xv.y,wk.y,ak[1]);
        aq[1]=fma2(xv.x,wq.x,aq[1]); aq[1]=fma2(xv.y,wq.y,aq[1]);
        av[1]=fma2(xv.x,wv.x,av[1]); av[1]=fma2(xv.y,wv.y,av[1]);
        xv = x2[c4];
        ak[2]=fma2(xv.x,wk.x,ak[2]); ak[2]=fma2(xv.y,wk.y,ak[2]);
        aq[2]=fma2(xv.x,wq.x,aq[2]); aq[2]=fma2(xv.y,wq.y,aq[2]);
        av[2]=fma2(xv.x,wv.x,av[2]); av[2]=fma2(xv.y,wv.y,av[2]);
        xv = x3[c4];
        ak[3]=fma2(xv.x,wk.x,ak[3]); ak[3]=fma2(xv.y,wk.y,ak[3]);
        aq[3]=fma2(xv.x,wq.x,aq[3]); aq[3]=fma2(xv.y,wq.y,aq[3]);
        av[3]=fma2(xv.x,wv.x,av[3]); av[3]=fma2(xv.y,wv.y,av[3]);
    }
#pragma unroll
    for (int rr = 0; rr < 4; rr++) {
        int base = (row0 + r + rr * 8) * HS + h;
        float2 f;
        f = unpack2(ak[rr]); g_k[base] = f.x + f.y;
        f = unpack2(aq[rr]); g_q[base] = f.x + f.y;
        f = unpack2(av[rr]); g_v[base] = f.x + f.y;
    }
}

// -------------------------------------------------------------------------
// Attention partials. weights = k @ q^T (reference quirk), causal s <= t,
// no max-subtraction (scores O(5), fp32-safe): split-s partials add.
// Each thread owns TWO t rows (tid and tid+128 of a 256-row tile) so the
// broadcast q/v smem reads amortize over 64 (t,s) pairs per warp-j.
// Off-diagonal chunks are branch-free full loops.
// -------------------------------------------------------------------------
__device__ __forceinline__ void dot8(const ulonglong2* __restrict__ kt,
                                     const ulonglong2* __restrict__ qj,
                                     float& outp) {
    u64 a0 = 0, a1 = 0, a2 = 0, a3 = 0;
#pragma unroll
    for (int i = 0; i < 8; i += 2) {
        ulonglong2 q0 = qj[i], q1 = qj[i + 1];
        a0 = fma2(kt[i].x,     q0.x, a0);
        a1 = fma2(kt[i].y,     q0.y, a1);
        a2 = fma2(kt[i + 1].x, q1.x, a2);
        a3 = fma2(kt[i + 1].y, q1.y, a3);
    }
    float2 f = unpack2(add2(add2(a0, a1), add2(a2, a3)));
    outp = f.x + f.y;
}

__global__ void __launch_bounds__(NTHR, 2) attn_kernel() {
    int pr = g_pairs[blockIdx.x];
    int tile = pr & 0xff;
    int c = pr >> 8;
    int b = blockIdx.y;
    int t0 = tile * TROWS;
    int tA = t0 + threadIdx.x;          // lower row
    int tB = tA + 128;                  // upper row
    size_t rowbase = (size_t)b * TT;

    ulonglong2 ktA[8], ktB[8];
    {
        const ulonglong2* ka = (const ulonglong2*)(g_k + (rowbase + tA) * HS);
        const ulonglong2* kb = (const ulonglong2*)(g_k + (rowbase + tB) * HS);
#pragma unroll
        for (int i = 0; i < 8; i++) { ktA[i] = ka[i]; ktB[i] = kb[i]; }
    }

    ulonglong2 accA[8], accB[8];
#pragma unroll
    for (int i = 0; i < 8; i++) {
        accA[i].x = 0ull; accA[i].y = 0ull;
        accB[i].x = 0ull; accB[i].y = 0ull;
    }
    float denA = 0.f, denB = 0.f;

    __shared__ ulonglong2 qs[TSW * 8];
    __shared__ ulonglong2 vs[TSW * 8];

    int s_begin = c * SC;
    bool full = (c < tile);

    for (int s0 = s_begin; s0 < s_begin + SC; s0 += TSW) {
        __syncthreads();
        const ulonglong2* q2 = (const ulonglong2*)(g_q + (rowbase + s0) * HS);
        const ulonglong2* v2 = (const ulonglong2*)(g_v + (rowbase + s0) * HS);
#pragma unroll
        for (int k = 0; k < 8; k++) {
            int i = threadIdx.x + k * NTHR;
            qs[i] = q2[i];
            vs[i] = v2[i];
        }
        __syncthreads();

        if (full) {
            // both rows take all 128 s positions
            for (int j = 0; j < TSW; j++) {
                const ulonglong2* qj = qs + j * 8;
                float sA, sB;
                dot8(ktA, qj, sA);
                dot8(ktB, qj, sB);
                float pA = __expf(sA);
                float pB = __expf(sB);
                denA += pA; denB += pB;
                u64 ppA = pack2(pA, pA), ppB = pack2(pB, pB);
                const ulonglong2* vj = vs + j * 8;
#pragma unroll
                for (int i = 0; i < 8; i++) {
                    ulonglong2 vv = vj[i];
                    accA[i].x = fma2(ppA, vv.x, accA[i].x);
                    accA[i].y = fma2(ppA, vv.y, accA[i].y);
                    accB[i].x = fma2(ppB, vv.x, accB[i].x);
                    accB[i].y = fma2(ppB, vv.y, accB[i].y);
                }
            }
        } else {
            int jA = tA - s0 + 1;
            if (jA < 0) jA = 0; if (jA > TSW) jA = TSW;
            int jB = tB - s0 + 1;
            if (jB < 0) jB = 0; if (jB > TSW) jB = TSW;
            int j = 0;
            for (; j < jA; j++) {
                const ulonglong2* qj = qs + j * 8;
                float sA, sB;
                dot8(ktA, qj, sA);
                dot8(ktB, qj, sB);
                float pA = __expf(sA);
                float pB = __expf(sB);
                denA += pA; denB += pB;
                u64 ppA = pack2(pA, pA), ppB = pack2(pB, pB);
                const ulonglong2* vj = vs + j * 8;
#pragma unroll
                for (int i = 0; i < 8; i++) {
                    ulonglong2 vv = vj[i];
                    accA[i].x = fma2(ppA, vv.x, accA[i].x);
                    accA[i].y = fma2(ppA, vv.y, accA[i].y);
                    accB[i].x = fma2(ppB, vv.x, accB[i].x);
                    accB[i].y = fma2(ppB, vv.y, accB[i].y);
                }
            }
            for (; j < jB; j++) {
                const ulonglong2* qj = qs + j * 8;
                float sB;
                dot8(ktB, qj, sB);
                float pB = __expf(sB);
                denB += pB;
                u64 ppB = pack2(pB, pB);
                const ulonglong2* vj = vs + j * 8;
#pragma unroll
                for (int i = 0; i < 8; i++) {
                    ulonglong2 vv = vj[i];
                    accB[i].x = fma2(ppB, vv.x, accB[i].x);
                    accB[i].y = fma2(ppB, vv.y, accB[i].y);
                }
            }
        }
    }

    size_t rowA = rowbase + tA;
    size_t rowB = rowbase + tB;
    ulonglong2* pa = (ulonglong2*)(g_pacc + ((size_t)c * NROWS + rowA) * HS);
    ulonglong2* pb = (ulonglong2*)(g_pacc + ((size_t)c * NROWS + rowB) * HS);
#pragma unroll
    for (int i = 0; i < 8; i++) { pa[i] = accA[i]; pb[i] = accB[i]; }
    g_pden[c * NROWS + rowA] = denA;
    g_pden[c * NROWS + rowB] = denB;
}

// -------------------------------------------------------------------------
// Combine split-s partials and normalize. One float4 per thread.
// -------------------------------------------------------------------------
__global__ void combine_kernel(float* __restrict__ out) {
    int gid = blockIdx.x * 256 + threadIdx.x;     // NROWS*8 threads
    int row = gid >> 3;
    int q = gid & 7;
    int t = row & (TT - 1);
    int cmax = t / SC;
    float4 a = make_float4(0.f, 0.f, 0.f, 0.f);
    float den = 0.f;
    const float4* pacc4 = (const float4*)g_pacc;
    for (int c = 0; c <= cmax; c++) {
        den += g_pden[c * NROWS + row];
        float4 v = pacc4[((size_t)c * NROWS + row) * 8 + q];
        a.x += v.x; a.y += v.y; a.z += v.z; a.w += v.w;
    }
    float rinv = 1.f / den;
    ((float4*)out)[(size_t)row * 8 + q] =
        make_float4(a.x * rinv, a.y * rinv, a.z * rinv, a.w * rinv);
}

extern "C" void kernel_launch(void* const* d_in, const int* in_sizes, int n_in,
                              void* d_out, int out_size) {
    const float* x  = (const float*)d_in[0];
    const float* Wk = (const float*)d_in[1];
    const float* Wq = (const float*)d_in[2];
    const float* Wv = (const float*)d_in[3];
    float* out = (float*)d_out;

    prepack_kernel<<<(3 * CC4 * HS + 255) / 256, 256>>>(Wk, Wq, Wv);

    dim3 pb(32, 8);
    proj_kernel<<<NROWS / PR, pb>>>(x);

    dim3 ag(36, BB);
    attn_kernel<<<ag, NTHR>>>();

    combine_kernel<<<NROWS * 8 / 256, 256>>>(out);
}

// round 7
// speedup vs baseline: 1.5586x; 1.5586x over previous
#include <cuda_runtime.h>
#include <cuda_bf16.h>

#define BB 16
#define TT 2048
#define CC 288
#define CC4 (CC/4)
#define HS 32
#define NROWS (BB*TT)
#define QKSCALE 0.17677669529663687f   // 32^-0.5, folded into Wk

typedef unsigned long long u64;
typedef unsigned int u32;

// ---- scratch (device globals; cudaMalloc forbidden) ----
// K,Q split rows: 64 bf16 per row = 128B: cols 0-31 hi, 32-63 lo.
__device__ __align__(16) __nv_bfloat16 g_kspl[NROWS*64];
__device__ __align__(16) __nv_bfloat16 g_qspl[NROWS*64];
// V transposed: [b][h][s], hi and lo parts.
__device__ __align__(16) __nv_bfloat16 g_vth[BB*HS*TT];
__device__ __align__(16) __nv_bfloat16 g_vtl[BB*HS*TT];
__device__ ulonglong2 g_wq[3*CC4*HS];            // packed W quads

// ---- packed f32x2 helpers (proj) ----
__device__ __forceinline__ u64 fma2(u64 a, u64 b, u64 c) {
    u64 d; asm("fma.rn.f32x2 %0,%1,%2,%3;" : "=l"(d) : "l"(a), "l"(b), "l"(c)); return d;
}
__device__ __forceinline__ u64 pack2(float lo, float hi) {
    u64 d; asm("mov.b64 %0,{%1,%2};" : "=l"(d) : "f"(lo), "f"(hi)); return d;
}
__device__ __forceinline__ float2 unpack2(u64 a) {
    float lo, hi; asm("mov.b64 {%0,%1},%2;" : "=f"(lo), "=f"(hi) : "l"(a));
    return make_float2(lo, hi);
}
__device__ __forceinline__ u32 packbf(__nv_bfloat16 a, __nv_bfloat16 b) {
    return ((u32)__bfloat16_as_ushort(b) << 16) | (u32)__bfloat16_as_ushort(a);
}

// Baseline bf16 tensor-core MMA (sm_80+ PTX; runs on sm_103 HMMA pipe).
__device__ __forceinline__ void mma_bf16(float* d, const u32* a, const u32* b) {
    asm volatile(
        "mma.sync.aligned.m16n8k16.row.col.f32.bf16.bf16.f32 "
        "{%0,%1,%2,%3}, {%4,%5,%6,%7}, {%8,%9}, {%0,%1,%2,%3};"
        : "+f"(d[0]), "+f"(d[1]), "+f"(d[2]), "+f"(d[3])
        : "r"(a[0]), "r"(a[1]), "r"(a[2]), "r"(a[3]), "r"(b[0]), "r"(b[1]));
}

// -------------------------------------------------------------------------
// Prepack: W quads, c-major per h lane. Wk pre-scaled by 32^-0.5.
// -------------------------------------------------------------------------
__global__ void prepack_kernel(const float* __restrict__ Wk,
                               const float* __restrict__ Wq,
                               const float* __restrict__ Wv) {
    int i = blockIdx.x * 256 + threadIdx.x;
    if (i >= 3 * CC4 * HS) return;
    int h = i & (HS - 1);
    int c4 = (i >> 5) % CC4;
    int p = i / (CC4 * HS);
    const float* W = (p == 0) ? Wk : (p == 1) ? Wq : Wv;
    float s = (p == 0) ? QKSCALE : 1.0f;
    float w0 = W[(4 * c4 + 0) * HS + h] * s;
    float w1 = W[(4 * c4 + 1) * HS + h] * s;
    float w2 = W[(4 * c4 + 2) * HS + h] * s;
    float w3 = W[(4 * c4 + 3) * HS + h] * s;
    ulonglong2 r; r.x = pack2(w0, w1); r.y = pack2(w2, w3);
    g_wq[i] = r;
}

// -------------------------------------------------------------------------
// Projection (f32x2, round-4 structure) + bf16 hi/lo split outputs,
// V written transposed ([b][h][t]) for the PV MMA's .col B operand.
// -------------------------------------------------------------------------
#define PR 32
__global__ void proj_kernel(const float* __restrict__ x) {
    __shared__ ulonglong2 xs[PR * CC4];                      // 36 KB
    __shared__ __align__(16) __nv_bfloat16 vth_s[HS * 32];   // 2 KB
    __shared__ __align__(16) __nv_bfloat16 vtl_s[HS * 32];   // 2 KB
    int row0 = blockIdx.x * PR;
    int tid = threadIdx.y * 32 + threadIdx.x;
    const ulonglong2* xr = (const ulonglong2*)(x + (size_t)row0 * CC);
    for (int i = tid; i < PR * CC4; i += 256) xs[i] = xr[i];
    __syncthreads();

    int h = threadIdx.x, r = threadIdx.y;
    const ulonglong2* x0 = xs + (r)      * CC4;
    const ulonglong2* x1 = xs + (r + 8)  * CC4;
    const ulonglong2* x2 = xs + (r + 16) * CC4;
    const ulonglong2* x3 = xs + (r + 24) * CC4;

    u64 ak[4] = {0,0,0,0}, aq[4] = {0,0,0,0}, av[4] = {0,0,0,0};
#pragma unroll 4
    for (int c4 = 0; c4 < CC4; c4++) {
        ulonglong2 wk = g_wq[(0 * CC4 + c4) * HS + h];
        ulonglong2 wq = g_wq[(1 * CC4 + c4) * HS + h];
        ulonglong2 wv = g_wq[(2 * CC4 + c4) * HS + h];
        ulonglong2 xv;
        xv = x0[c4];
        ak[0]=fma2(xv.x,wk.x,ak[0]); ak[0]=fma2(xv.y,wk.y,ak[0]);
        aq[0]=fma2(xv.x,wq.x,aq[0]); aq[0]=fma2(xv.y,wq.y,aq[0]);
        av[0]=fma2(xv.x,wv.x,av[0]); av[0]=fma2(xv.y,wv.y,av[0]);
        xv = x1[c4];
        ak[1]=fma2(xv.x,wk.x,ak[1]); ak[1]=fma2(xv.y,wk.y,ak[1]);
        aq[1]=fma2(xv.x,wq.x,aq[1]); aq[1]=fma2(xv.y,wq.y,aq[1]);
        av[1]=fma2(xv.x,wv.x,av[1]); av[1]=fma2(xv.y,wv.y,av[1]);
        xv = x2[c4];
        ak[2]=fma2(xv.x,wk.x,ak[2]); ak[2]=fma2(xv.y,wk.y,ak[2]);
        aq[2]=fma2(xv.x,wq.x,aq[2]); aq[2]=fma2(xv.y,wq.y,aq[2]);
        av[2]=fma2(xv.x,wv.x,av[2]); av[2]=fma2(xv.y,wv.y,av[2]);
        xv = x3[c4];
        ak[3]=fma2(xv.x,wk.x,ak[3]); ak[3]=fma2(xv.y,wk.y,ak[3]);
        aq[3]=fma2(xv.x,wq.x,aq[3]); aq[3]=fma2(xv.y,wq.y,aq[3]);
        av[3]=fma2(xv.x,wv.x,av[3]); av[3]=fma2(xv.y,wv.y,av[3]);
    }
#pragma unroll
    for (int rr = 0; rr < 4; rr++) {
        int tl = r + rr * 8;
        size_t row = row0 + tl;
        float2 f;
        f = unpack2(ak[rr]); float kv = f.x + f.y;
        f = unpack2(aq[rr]); float qv = f.x + f.y;
        f = unpack2(av[rr]); float vv = f.x + f.y;
        __nv_bfloat16 khi = __float2bfloat16(kv);
        __nv_bfloat16 klo = __float2bfloat16(kv - __bfloat162float(khi));
        g_kspl[row * 64 + h]      = khi;
        g_kspl[row * 64 + 32 + h] = klo;
        __nv_bfloat16 qhi = __float2bfloat16(qv);
        __nv_bfloat16 qlo = __float2bfloat16(qv - __bfloat162float(qhi));
        g_qspl[row * 64 + h]      = qhi;
        g_qspl[row * 64 + 32 + h] = qlo;
        __nv_bfloat16 vhi = __float2bfloat16(vv);
        __nv_bfloat16 vlo = __float2bfloat16(vv - __bfloat162float(vhi));
        vth_s[h * 32 + tl] = vhi;
        vtl_s[h * 32 + tl] = vlo;
    }
    __syncthreads();
    // coalesced transposed V writeback: [b][h][t]
    int b = row0 >> 11, tin = row0 & (TT - 1);
    if (tid < 128) {
        int hh = tid >> 2, seg = tid & 3;
        uint4 v = *(const uint4*)(vth_s + hh * 32 + seg * 8);
        *(uint4*)(g_vth + ((size_t)(b * HS + hh)) * TT + tin + seg * 8) = v;
    } else {
        int t2 = tid - 128; int hh = t2 >> 2, seg = t2 & 3;
        uint4 v = *(const uint4*)(vtl_s + hh * 32 + seg * 8);
        *(uint4*)(g_vtl + ((size_t)(b * HS + hh)) * TT + tin + seg * 8) = v;
    }
}

// -------------------------------------------------------------------------
// Flash attention on mma.sync (HMMA). One CTA per (b, 128-row t-tile),
// 8 warps x 16 rows. weights = k @ q^T (reference quirk): A = K rows,
// B = Q rows (.col layout). hi/lo bf16 split x3 MMAs per GEMM. S-accum
// fragments feed the PV MMA A-operand directly in registers (FA2 trick).
// No max-subtraction (scores O(5), fp32-safe).
// -------------------------------------------------------------------------
#define KSTR 72     // padded row stride (bf16) for K/Q tiles: conflict-free
#define VSTR 136    // padded row stride for Vt tiles
#define SMEMB ((256*KSTR + 64*VSTR) * 2)

__global__ void __launch_bounds__(256) attn_mma(float* __restrict__ out) {
    extern __shared__ __nv_bfloat16 sm[];
    __nv_bfloat16* ks  = sm;
    __nv_bfloat16* qs  = sm + 128 * KSTR;
    __nv_bfloat16* vhs = sm + 256 * KSTR;
    __nv_bfloat16* vls = sm + 256 * KSTR + 32 * VSTR;

    int tid = threadIdx.x, wid = tid >> 5, lane = tid & 31;
    int qr = lane >> 2, qc = (lane & 3) << 1;
    int tile = 15 - (int)(blockIdx.x >> 4);     // longest first
    int b = blockIdx.x & 15;
    int t0 = tile << 7;
    int r1 = (wid << 4) + qr;
    int trow1 = t0 + r1, trow2 = trow1 + 8;

    // ---- K tile: global -> padded smem (once) ----
    {
        const uint4* kg = (const uint4*)(g_kspl + ((size_t)(b * TT + t0)) * 64);
        for (int i = tid; i < 1024; i += 256) {
            int row = i >> 3, seg = i & 7;
            *(uint4*)(ks + row * KSTR + seg * 8) = kg[row * 8 + seg];
        }
    }
    __syncthreads();

    // ---- K fragments in registers: [split][kk][4] ----
    u32 aK[2][2][4];
#pragma unroll
    for (int sp = 0; sp < 2; sp++)
#pragma unroll
        for (int kk = 0; kk < 2; kk++) {
            int c = sp * 32 + kk * 16 + qc;
            aK[sp][kk][0] = *(const u32*)(ks + r1 * KSTR + c);
            aK[sp][kk][1] = *(const u32*)(ks + (r1 + 8) * KSTR + c);
            aK[sp][kk][2] = *(const u32*)(ks + r1 * KSTR + c + 8);
            aK[sp][kk][3] = *(const u32*)(ks + (r1 + 8) * KSTR + c + 8);
        }

    float oacc[4][4];
#pragma unroll
    for (int i = 0; i < 4; i++)
#pragma unroll
        for (int j = 0; j < 4; j++) oacc[i][j] = 0.f;
    float den1 = 0.f, den2 = 0.f;

    for (int st = 0; st <= tile; st++) {
        int s0 = st << 7;
        __syncthreads();
        // ---- Q tile ----
        {
            const uint4* qg = (const uint4*)(g_qspl + ((size_t)(b * TT + s0)) * 64);
            for (int i = tid; i < 1024; i += 256) {
                int row = i >> 3, seg = i & 7;
                *(uint4*)(qs + row * KSTR + seg * 8) = qg[row * 8 + seg];
            }
        }
        // ---- Vt hi/lo tiles ----
        for (int i = tid; i < 512; i += 256) {
            int row = i >> 4, seg = i & 15;
            size_t base = ((size_t)(b * HS + row)) * TT + s0;
            *(uint4*)(vhs + row * VSTR + seg * 8) = *((const uint4*)(g_vth + base) + seg);
            *(uint4*)(vls + row * VSTR + seg * 8) = *((const uint4*)(g_vtl + base) + seg);
        }
        __syncthreads();

        bool diag = (st == tile);
#pragma unroll 1
        for (int ch = 0; ch < 4; ch++) {
            // ---- S = K.Q^T for 32 s-cols ----
            float sacc[4][4];
#pragma unroll
            for (int i = 0; i < 4; i++)
#pragma unroll
                for (int j = 0; j < 4; j++) sacc[i][j] = 0.f;
#pragma unroll
            for (int kk = 0; kk < 2; kk++) {
#pragma unroll
                for (int nt = 0; nt < 4; nt++) {
                    int srow = ch * 32 + nt * 8 + qr;
                    const __nv_bfloat16* qrow = qs + srow * KSTR + kk * 16 + qc;
                    u32 bh[2], bl[2];
                    bh[0] = *(const u32*)(qrow);
                    bh[1] = *(const u32*)(qrow + 8);
                    bl[0] = *(const u32*)(qrow + 32);
                    bl[1] = *(const u32*)(qrow + 40);
                    mma_bf16(sacc[nt], aK[0][kk], bh);   // hi*hi
                    mma_bf16(sacc[nt], aK[1][kk], bh);   // lo*hi
                    mma_bf16(sacc[nt], aK[0][kk], bl);   // hi*lo
                }
            }
            // ---- exp epilogue -> P fragments (registers only) ----
            u32 pha[2][4], pla[2][4];
            int scb = s0 + ch * 32;
#pragma unroll
            for (int nt = 0; nt < 4; nt++) {
                int c0 = scb + nt * 8 + qc;
                float p0, p1, p2, p3;
                if (diag) {
                    p0 = (c0     <= trow1) ? __expf(sacc[nt][0]) : 0.f;
                    p1 = (c0 + 1 <= trow1) ? __expf(sacc[nt][1]) : 0.f;
                    p2 = (c0     <= trow2) ? __expf(sacc[nt][2]) : 0.f;
                    p3 = (c0 + 1 <= trow2) ? __expf(sacc[nt][3]) : 0.f;
                } else {
                    p0 = __expf(sacc[nt][0]);
                    p1 = __expf(sacc[nt][1]);
                    p2 = __expf(sacc[nt][2]);
                    p3 = __expf(sacc[nt][3]);
                }
                den1 += p0 + p1;
                den2 += p2 + p3;
                __nv_bfloat16 h0 = __float2bfloat16(p0), h1 = __float2bfloat16(p1);
                __nv_bfloat16 h2 = __float2bfloat16(p2), h3 = __float2bfloat16(p3);
                int j = nt >> 1, o = (nt & 1) << 1;
                pha[j][o]     = packbf(h0, h1);
                pha[j][o + 1] = packbf(h2, h3);
                pla[j][o]     = packbf(__float2bfloat16(p0 - __bfloat162float(h0)),
                                       __float2bfloat16(p1 - __bfloat162float(h1)));
                pla[j][o + 1] = packbf(__float2bfloat16(p2 - __bfloat162float(h2)),
                                       __float2bfloat16(p3 - __bfloat162float(h3)));
            }
            // ---- O += P.V ----
#pragma unroll
            for (int j = 0; j < 2; j++) {
                int kb = ch * 32 + j * 16 + qc;
#pragma unroll
                for (int hnt = 0; hnt < 4; hnt++) {
                    int h = hnt * 8 + qr;
                    const __nv_bfloat16* vr  = vhs + h * VSTR + kb;
                    const __nv_bfloat16* vr2 = vls + h * VSTR + kb;
                    u32 bvh[2], bvl[2];
                    bvh[0] = *(const u32*)(vr);
                    bvh[1] = *(const u32*)(vr + 8);
                    bvl[0] = *(const u32*)(vr2);
                    bvl[1] = *(const u32*)(vr2 + 8);
                    mma_bf16(oacc[hnt], pha[j], bvh);    // ph*vh
                    mma_bf16(oacc[hnt], pla[j], bvh);    // pl*vh
                    mma_bf16(oacc[hnt], pha[j], bvl);    // ph*vl
                }
            }
        }
    }

    // ---- denominators: reduce across the 4 lanes sharing each row ----
    den1 += __shfl_xor_sync(0xffffffffu, den1, 1);
    den1 += __shfl_xor_sync(0xffffffffu, den1, 2);
    den2 += __shfl_xor_sync(0xffffffffu, den2, 1);
    den2 += __shfl_xor_sync(0xffffffffu, den2, 2);
    float rinv1 = 1.f / den1, rinv2 = 1.f / den2;

    float* o1 = out + ((size_t)(b * TT + trow1)) * HS;
    float* o2 = out + ((size_t)(b * TT + trow2)) * HS;
#pragma unroll
    for (int hnt = 0; hnt < 4; hnt++) {
        int col = hnt * 8 + qc;
        *(float2*)(o1 + col) = make_float2(oacc[hnt][0] * rinv1, oacc[hnt][1] * rinv1);
        *(float2*)(o2 + col) = make_float2(oacc[hnt][2] * rinv2, oacc[hnt][3] * rinv2);
    }
}

extern "C" void kernel_launch(void* const* d_in, const int* in_sizes, int n_in,
                              void* d_out, int out_size) {
    const float* x  = (const float*)d_in[0];
    const float* Wk = (const float*)d_in[1];
    const float* Wq = (const float*)d_in[2];
    const float* Wv = (const float*)d_in[3];
    float* out = (float*)d_out;

    prepack_kernel<<<(3 * CC4 * HS + 255) / 256, 256>>>(Wk, Wq, Wv);

    dim3 pb(32, 8);
    proj_kernel<<<NROWS / PR, pb>>>(x);

    cudaFuncSetAttribute(attn_mma, cudaFuncAttributeMaxDynamicSharedMemorySize, SMEMB);
    attn_mma<<<256, 256, SMEMB>>>(out);
}

// round 8
// speedup vs baseline: 1.7278x; 1.1085x over previous
#include <cuda_runtime.h>
#include <cuda_bf16.h>

#define BB 16
#define TT 2048
#define CC 288
#define HS 32
#define NROWS (BB*TT)
#define NKS (CC/16)      // 18 K-steps
#define QKSCALE 0.17677669529663687f   // 32^-0.5, folded into Wk

typedef unsigned long long u64;
typedef unsigned int u32;

// ---- scratch (device globals; cudaMalloc forbidden) ----
// K,Q split rows: 64 bf16 per row = 128B: cols 0-31 hi, 32-63 lo.
__device__ __align__(16) __nv_bfloat16 g_kspl[NROWS*64];
__device__ __align__(16) __nv_bfloat16 g_qspl[NROWS*64];
// V transposed: [b][h][s], hi and lo parts.
__device__ __align__(16) __nv_bfloat16 g_vth[BB*HS*TT];
__device__ __align__(16) __nv_bfloat16 g_vtl[BB*HS*TT];
// W as ready B-fragments: [p][ks][n][tig] -> u64 {b0=pack(W[c0],W[c0+1]), b1=pack(W[c0+8],W[c0+9])}
__device__ u64 g_wbh[3*NKS*32*4];
__device__ u64 g_wbl[3*NKS*32*4];

__device__ __forceinline__ u32 packbf(__nv_bfloat16 a, __nv_bfloat16 b) {
    return ((u32)__bfloat16_as_ushort(b) << 16) | (u32)__bfloat16_as_ushort(a);
}

// Baseline bf16 tensor-core MMA (sm_80+ PTX; HMMA pipe).
__device__ __forceinline__ void mma_bf16(float* d, const u32* a, const u32* b) {
    asm volatile(
        "mma.sync.aligned.m16n8k16.row.col.f32.bf16.bf16.f32 "
        "{%0,%1,%2,%3}, {%4,%5,%6,%7}, {%8,%9}, {%0,%1,%2,%3};"
        : "+f"(d[0]), "+f"(d[1]), "+f"(d[2]), "+f"(d[3])
        : "r"(a[0]), "r"(a[1]), "r"(a[2]), "r"(a[3]), "r"(b[0]), "r"(b[1]));
}

// -------------------------------------------------------------------------
// Prepack: W -> bf16 hi/lo B-fragment u64s, QKSCALE folded into Wk.
// Index i = ((p*NKS + ks)*32 + n)*4 + tig; c0 = ks*16 + tig*2.
// -------------------------------------------------------------------------
__global__ void prepack_kernel(const float* __restrict__ Wk,
                               const float* __restrict__ Wq,
                               const float* __restrict__ Wv) {
    int i = blockIdx.x * 256 + threadIdx.x;
    if (i >= 3 * NKS * 32 * 4) return;
    int tig = i & 3;
    int n = (i >> 2) & 31;
    int ks = (i >> 7) % NKS;
    int p = i / (NKS * 32 * 4);
    const float* W = (p == 0) ? Wk : (p == 1) ? Wq : Wv;
    float s = (p == 0) ? QKSCALE : 1.0f;
    int c0 = ks * 16 + tig * 2;
    float w[4];
    w[0] = W[(c0)     * HS + n] * s;
    w[1] = W[(c0 + 1) * HS + n] * s;
    w[2] = W[(c0 + 8) * HS + n] * s;
    w[3] = W[(c0 + 9) * HS + n] * s;
    __nv_bfloat16 h[4]; float l[4];
#pragma unroll
    for (int j = 0; j < 4; j++) { h[j] = __float2bfloat16(w[j]); l[j] = w[j] - __bfloat162float(h[j]); }
    g_wbh[i] = ((u64)packbf(h[2], h[3]) << 32) | (u64)packbf(h[0], h[1]);
    g_wbl[i] = ((u64)packbf(__float2bfloat16(l[2]), __float2bfloat16(l[3])) << 32)
             | (u64)packbf(__float2bfloat16(l[0]), __float2bfloat16(l[1]));
}

// -------------------------------------------------------------------------
// Tensor-core projection. One CTA per 64 x-rows. x converted to bf16 hi/lo
// in smem (stride 296: conflict-free A-frag LDS). 8 warps: warp = 16-row
// strip (wid&3) x unit-half (wid>>2); 12 (proj, n-tile) units split 6/6.
// Per K-step: 8 LDS (A hi/lo frags) + 12 LDG.64 (W frags) + 18 MMAs.
// Outputs: K/Q hi/lo split rows; V transposed hi/lo via smem stage.
// -------------------------------------------------------------------------
#define XSTR 296
#define PSM ((64*XSTR*2 + 2*2048) * 2)   // xhi + xlo + vsh + vsl (bytes)

__global__ void __launch_bounds__(256) proj_mma(const float* __restrict__ x) {
    extern __shared__ __nv_bfloat16 psm[];
    __nv_bfloat16* xhi = psm;
    __nv_bfloat16* xlo = psm + 64 * XSTR;
    __nv_bfloat16* vsh = psm + 128 * XSTR;
    __nv_bfloat16* vsl = psm + 128 * XSTR + 2048;

    int tid = threadIdx.x;
    int row0 = blockIdx.x * 64;

    // ---- load x, convert to bf16 hi/lo ----
    {
        const float4* xg = (const float4*)(x + (size_t)row0 * CC);
        for (int i = tid; i < 64 * 72; i += 256) {
            int row = i / 72, c4 = i % 72;
            float4 v = xg[i];
            __nv_bfloat16 h0 = __float2bfloat16(v.x), h1 = __float2bfloat16(v.y);
            __nv_bfloat16 h2 = __float2bfloat16(v.z), h3 = __float2bfloat16(v.w);
            *(uint2*)(xhi + row * XSTR + c4 * 4) =
                make_uint2(packbf(h0, h1), packbf(h2, h3));
            *(uint2*)(xlo + row * XSTR + c4 * 4) = make_uint2(
                packbf(__float2bfloat16(v.x - __bfloat162float(h0)),
                       __float2bfloat16(v.y - __bfloat162float(h1))),
                packbf(__float2bfloat16(v.z - __bfloat162float(h2)),
                       __float2bfloat16(v.w - __bfloat162float(h3))));
        }
    }
    __syncthreads();

    int wid = tid >> 5, lane = tid & 31;
    int g = lane >> 2, tig = lane & 3;
    int rs = wid & 3, half = wid >> 2;
    int arow = rs * 16 + g;

    float oacc[6][4];
#pragma unroll
    for (int u = 0; u < 6; u++)
#pragma unroll
        for (int j = 0; j < 4; j++) oacc[u][j] = 0.f;

    for (int ks = 0; ks < NKS; ks++) {
        int cb = ks * 16;
        u32 ah[4], al[4];
        ah[0] = *(const u32*)(xhi + arow * XSTR + cb + 2 * tig);
        ah[1] = *(const u32*)(xhi + (arow + 8) * XSTR + cb + 2 * tig);
        ah[2] = *(const u32*)(xhi + arow * XSTR + cb + 8 + 2 * tig);
        ah[3] = *(const u32*)(xhi + (arow + 8) * XSTR + cb + 8 + 2 * tig);
        al[0] = *(const u32*)(xlo + arow * XSTR + cb + 2 * tig);
        al[1] = *(const u32*)(xlo + (arow + 8) * XSTR + cb + 2 * tig);
        al[2] = *(const u32*)(xlo + arow * XSTR + cb + 8 + 2 * tig);
        al[3] = *(const u32*)(xlo + (arow + 8) * XSTR + cb + 8 + 2 * tig);
#pragma unroll
        for (int u = 0; u < 6; u++) {
            int idx = half * 6 + u;
            int p = idx >> 2, nt = idx & 3;
            int base = ((p * NKS + ks) * 32 + nt * 8 + g) * 4 + tig;
            u64 wh = g_wbh[base];
            u64 wl = g_wbl[base];
            u32 bh[2] = { (u32)wh, (u32)(wh >> 32) };
            u32 bl[2] = { (u32)wl, (u32)(wl >> 32) };
            mma_bf16(oacc[u], ah, bh);   // hi*hi
            mma_bf16(oacc[u], al, bh);   // lo*hi
            mma_bf16(oacc[u], ah, bl);   // hi*lo
        }
    }

    // ---- write K/Q split rows; stage V transposed ----
#pragma unroll
    for (int u = 0; u < 6; u++) {
        int idx = half * 6 + u;
        int p = idx >> 2, nt = idx & 3;
        int c0 = nt * 8 + 2 * tig;
        int rloc0 = rs * 16 + g;
#pragma unroll
        for (int rr = 0; rr < 2; rr++) {
            int rloc = rloc0 + rr * 8;
            float v0 = oacc[u][rr * 2], v1 = oacc[u][rr * 2 + 1];
            __nv_bfloat16 h0 = __float2bfloat16(v0), h1 = __float2bfloat16(v1);
            u32 hp = packbf(h0, h1);
            u32 lp = packbf(__float2bfloat16(v0 - __bfloat162float(h0)),
                            __float2bfloat16(v1 - __bfloat162float(h1)));
            if (p == 0) {
                size_t r = (size_t)(row0 + rloc) * 64;
                *(u32*)(g_kspl + r + c0) = hp;
                *(u32*)(g_kspl + r + 32 + c0) = lp;
            } else if (p == 1) {
                size_t r = (size_t)(row0 + rloc) * 64;
                *(u32*)(g_qspl + r + c0) = hp;
                *(u32*)(g_qspl + r + 32 + c0) = lp;
            } else {
                vsh[c0 * 64 + rloc] = h0;
                vsh[(c0 + 1) * 64 + rloc] = h1;
                vsl[c0 * 64 + rloc] = __ushort_as_bfloat16((unsigned short)(lp & 0xffff));
                vsl[(c0 + 1) * 64 + rloc] = __ushort_as_bfloat16((unsigned short)(lp >> 16));
            }
        }
    }
    __syncthreads();
    // ---- coalesced transposed V writeback: [b][h][t] ----
    {
        int b = row0 >> 11, tin = row0 & (TT - 1);
        int h = tid >> 3, seg = tid & 7;
        size_t gb = ((size_t)(b * HS + h)) * TT + tin + seg * 8;
        *(uint4*)(g_vth + gb) = *(const uint4*)(vsh + h * 64 + seg * 8);
        *(uint4*)(g_vtl + gb) = *(const uint4*)(vsl + h * 64 + seg * 8);
    }
}

// -------------------------------------------------------------------------
// Flash attention on mma.sync (unchanged from round 7, passing @ ~100us).
// -------------------------------------------------------------------------
#define KSTR 72
#define VSTR 136
#define SMEMB ((256*KSTR + 64*VSTR) * 2)

__global__ void __launch_bounds__(256) attn_mma(float* __restrict__ out) {
    extern __shared__ __nv_bfloat16 sm[];
    __nv_bfloat16* ks  = sm;
    __nv_bfloat16* qs  = sm + 128 * KSTR;
    __nv_bfloat16* vhs = sm + 256 * KSTR;
    __nv_bfloat16* vls = sm + 256 * KSTR + 32 * VSTR;

    int tid = threadIdx.x, wid = tid >> 5, lane = tid & 31;
    int qr = lane >> 2, qc = (lane & 3) << 1;
    int tile = 15 - (int)(blockIdx.x >> 4);     // longest first
    int b = blockIdx.x & 15;
    int t0 = tile << 7;
    int r1 = (wid << 4) + qr;
    int trow1 = t0 + r1, trow2 = trow1 + 8;

    {
        const uint4* kg = (const uint4*)(g_kspl + ((size_t)(b * TT + t0)) * 64);
        for (int i = tid; i < 1024; i += 256) {
            int row = i >> 3, seg = i & 7;
            *(uint4*)(ks + row * KSTR + seg * 8) = kg[row * 8 + seg];
        }
    }
    __syncthreads();

    u32 aK[2][2][4];
#pragma unroll
    for (int sp = 0; sp < 2; sp++)
#pragma unroll
        for (int kk = 0; kk < 2; kk++) {
            int c = sp * 32 + kk * 16 + qc;
            aK[sp][kk][0] = *(const u32*)(ks + r1 * KSTR + c);
            aK[sp][kk][1] = *(const u32*)(ks + (r1 + 8) * KSTR + c);
            aK[sp][kk][2] = *(const u32*)(ks + r1 * KSTR + c + 8);
            aK[sp][kk][3] = *(const u32*)(ks + (r1 + 8) * KSTR + c + 8);
        }

    float oacc[4][4];
#pragma unroll
    for (int i = 0; i < 4; i++)
#pragma unroll
        for (int j = 0; j < 4; j++) oacc[i][j] = 0.f;
    float den1 = 0.f, den2 = 0.f;

    for (int st = 0; st <= tile; st++) {
        int s0 = st << 7;
        __syncthreads();
        {
            const uint4* qg = (const uint4*)(g_qspl + ((size_t)(b * TT + s0)) * 64);
            for (int i = tid; i < 1024; i += 256) {
                int row = i >> 3, seg = i & 7;
                *(uint4*)(qs + row * KSTR + seg * 8) = qg[row * 8 + seg];
            }
        }
        for (int i = tid; i < 512; i += 256) {
            int row = i >> 4, seg = i & 15;
            size_t base = ((size_t)(b * HS + row)) * TT + s0;
            *(uint4*)(vhs + row * VSTR + seg * 8) = *((const uint4*)(g_vth + base) + seg);
            *(uint4*)(vls + row * VSTR + seg * 8) = *((const uint4*)(g_vtl + base) + seg);
        }
        __syncthreads();

        bool diag = (st == tile);
#pragma unroll 1
        for (int ch = 0; ch < 4; ch++) {
            float sacc[4][4];
#pragma unroll
            for (int i = 0; i < 4; i++)
#pragma unroll
                for (int j = 0; j < 4; j++) sacc[i][j] = 0.f;
#pragma unroll
            for (int kk = 0; kk < 2; kk++) {
#pragma unroll
                for (int nt = 0; nt < 4; nt++) {
                    int srow = ch * 32 + nt * 8 + qr;
                    const __nv_bfloat16* qrow = qs + srow * KSTR + kk * 16 + qc;
                    u32 bh[2], bl[2];
                    bh[0] = *(const u32*)(qrow);
                    bh[1] = *(const u32*)(qrow + 8);
                    bl[0] = *(const u32*)(qrow + 32);
                    bl[1] = *(const u32*)(qrow + 40);
                    mma_bf16(sacc[nt], aK[0][kk], bh);
                    mma_bf16(sacc[nt], aK[1][kk], bh);
                    mma_bf16(sacc[nt], aK[0][kk], bl);
                }
            }
            u32 pha[2][4], pla[2][4];
            int scb = s0 + ch * 32;
#pragma unroll
            for (int nt = 0; nt < 4; nt++) {
                int c0 = scb + nt * 8 + qc;
                float p0, p1, p2, p3;
                if (diag) {
                    p0 = (c0     <= trow1) ? __expf(sacc[nt][0]) : 0.f;
                    p1 = (c0 + 1 <= trow1) ? __expf(sacc[nt][1]) : 0.f;
                    p2 = (c0     <= trow2) ? __expf(sacc[nt][2]) : 0.f;
                    p3 = (c0 + 1 <= trow2) ? __expf(sacc[nt][3]) : 0.f;
                } else {
                    p0 = __expf(sacc[nt][0]);
                    p1 = __expf(sacc[nt][1]);
                    p2 = __expf(sacc[nt][2]);
                    p3 = __expf(sacc[nt][3]);
                }
                den1 += p0 + p1;
                den2 += p2 + p3;
                __nv_bfloat16 h0 = __float2bfloat16(p0), h1 = __float2bfloat16(p1);
                __nv_bfloat16 h2 = __float2bfloat16(p2), h3 = __float2bfloat16(p3);
                int j = nt >> 1, o = (nt & 1) << 1;
                pha[j][o]     = packbf(h0, h1);
                pha[j][o + 1] = packbf(h2, h3);
                pla[j][o]     = packbf(__float2bfloat16(p0 - __bfloat162float(h0)),
                                       __float2bfloat16(p1 - __bfloat162float(h1)));
                pla[j][o + 1] = packbf(__float2bfloat16(p2 - __bfloat162float(h2)),
                                       __float2bfloat16(p3 - __bfloat162float(h3)));
            }
#pragma unroll
            for (int j = 0; j < 2; j++) {
                int kb = ch * 32 + j * 16 + qc;
#pragma unroll
                for (int hnt = 0; hnt < 4; hnt++) {
                    int h = hnt * 8 + qr;
                    const __nv_bfloat16* vr  = vhs + h * VSTR + kb;
                    const __nv_bfloat16* vr2 = vls + h * VSTR + kb;
                    u32 bvh[2], bvl[2];
                    bvh[0] = *(const u32*)(vr);
                    bvh[1] = *(const u32*)(vr + 8);
                    bvl[0] = *(const u32*)(vr2);
                    bvl[1] = *(const u32*)(vr2 + 8);
                    mma_bf16(oacc[hnt], pha[j], bvh);
                    mma_bf16(oacc[hnt], pla[j], bvh);
                    mma_bf16(oacc[hnt], pha[j], bvl);
                }
            }
        }
    }

    den1 += __shfl_xor_sync(0xffffffffu, den1, 1);
    den1 += __shfl_xor_sync(0xffffffffu, den1, 2);
    den2 += __shfl_xor_sync(0xffffffffu, den2, 1);
    den2 += __shfl_xor_sync(0xffffffffu, den2, 2);
    float rinv1 = 1.f / den1, rinv2 = 1.f / den2;

    float* o1 = out + ((size_t)(b * TT + trow1)) * HS;
    float* o2 = out + ((size_t)(b * TT + trow2)) * HS;
#pragma unroll
    for (int hnt = 0; hnt < 4; hnt++) {
        int col = hnt * 8 + qc;
        *(float2*)(o1 + col) = make_float2(oacc[hnt][0] * rinv1, oacc[hnt][1] * rinv1);
        *(float2*)(o2 + col) = make_float2(oacc[hnt][2] * rinv2, oacc[hnt][3] * rinv2);
    }
}

extern "C" void kernel_launch(void* const* d_in, const int* in_sizes, int n_in,
                              void* d_out, int out_size) {
    const float* x  = (const float*)d_in[0];
    const float* Wk = (const float*)d_in[1];
    const float* Wq = (const float*)d_in[2];
    const float* Wv = (const float*)d_in[3];
    float* out = (float*)d_out;

    prepack_kernel<<<(3 * NKS * 32 * 4 + 255) / 256, 256>>>(Wk, Wq, Wv);

    cudaFuncSetAttribute(proj_mma, cudaFuncAttributeMaxDynamicSharedMemorySize, PSM);
    proj_mma<<<NROWS / 64, 256, PSM>>>(x);

    cudaFuncSetAttribute(attn_mma, cudaFuncAttributeMaxDynamicSharedMemorySize, SMEMB);
    attn_mma<<<256, 256, SMEMB>>>(out);
}

// round 9
// speedup vs baseline: 1.7531x; 1.0147x over previous
#include <cuda_runtime.h>
#include <cuda_bf16.h>

#define BB 16
#define TT 2048
#define CC 288
#define HS 32
#define NROWS (BB*TT)
#define NKS (CC/16)      // 18 K-steps
#define QKSCALE 0.17677669529663687f   // 32^-0.5, folded into Wk

typedef unsigned long long u64;
typedef unsigned int u32;

// ---- scratch (device globals; cudaMalloc forbidden) ----
__device__ __align__(16) __nv_bfloat16 g_kspl[NROWS*64];
__device__ __align__(16) __nv_bfloat16 g_qspl[NROWS*64];
__device__ __align__(16) __nv_bfloat16 g_vth[BB*HS*TT];
__device__ __align__(16) __nv_bfloat16 g_vtl[BB*HS*TT];
__device__ u64 g_wbh[3*NKS*32*4];
__device__ u64 g_wbl[3*NKS*32*4];

__device__ __forceinline__ u32 packbf(__nv_bfloat16 a, __nv_bfloat16 b) {
    return ((u32)__bfloat16_as_ushort(b) << 16) | (u32)__bfloat16_as_ushort(a);
}
__device__ __forceinline__ u32 smem_u32(const void* p) {
    u32 a; asm("{ .reg .u64 t; cvta.to.shared.u64 t, %1; cvt.u32.u64 %0, t; }" : "=r"(a) : "l"(p));
    return a;
}
// pack 2 f32 -> bf16x2 in one instruction (lo in low half)
__device__ __forceinline__ u32 cvt2bf(float hi, float lo) {
    u32 r; asm("cvt.rn.bf16x2.f32 %0,%1,%2;" : "=r"(r) : "f"(hi), "f"(lo)); return r;
}
// Baseline bf16 tensor-core MMA (sm_80+ PTX; HMMA pipe).
__device__ __forceinline__ void mma_bf16(float* d, const u32* a, const u32* b) {
    asm volatile(
        "mma.sync.aligned.m16n8k16.row.col.f32.bf16.bf16.f32 "
        "{%0,%1,%2,%3}, {%4,%5,%6,%7}, {%8,%9}, {%0,%1,%2,%3};"
        : "+f"(d[0]), "+f"(d[1]), "+f"(d[2]), "+f"(d[3])
        : "r"(a[0]), "r"(a[1]), "r"(a[2]), "r"(a[3]), "r"(b[0]), "r"(b[1]));
}
// ldmatrix x4: four 8x8 b16 tiles, per-lane row addresses (lanes 0-7 m0, 8-15 m1, ...)
__device__ __forceinline__ void ldsm4(u32& r0, u32& r1, u32& r2, u32& r3, u32 addr) {
    asm volatile("ldmatrix.sync.aligned.m8n8.x4.shared.b16 {%0,%1,%2,%3}, [%4];"
                 : "=r"(r0), "=r"(r1), "=r"(r2), "=r"(r3) : "r"(addr));
}

// -------------------------------------------------------------------------
// Prepack: W -> bf16 hi/lo B-fragment u64s, QKSCALE folded into Wk.
// -------------------------------------------------------------------------
__global__ void prepack_kernel(const float* __restrict__ Wk,
                               const float* __restrict__ Wq,
                               const float* __restrict__ Wv) {
    int i = blockIdx.x * 256 + threadIdx.x;
    if (i >= 3 * NKS * 32 * 4) return;
    int tig = i & 3;
    int n = (i >> 2) & 31;
    int ks = (i >> 7) % NKS;
    int p = i / (NKS * 32 * 4);
    const float* W = (p == 0) ? Wk : (p == 1) ? Wq : Wv;
    float s = (p == 0) ? QKSCALE : 1.0f;
    int c0 = ks * 16 + tig * 2;
    float w[4];
    w[0] = W[(c0)     * HS + n] * s;
    w[1] = W[(c0 + 1) * HS + n] * s;
    w[2] = W[(c0 + 8) * HS + n] * s;
    w[3] = W[(c0 + 9) * HS + n] * s;
    __nv_bfloat16 h[4]; float l[4];
#pragma unroll
    for (int j = 0; j < 4; j++) { h[j] = __float2bfloat16(w[j]); l[j] = w[j] - __bfloat162float(h[j]); }
    g_wbh[i] = ((u64)packbf(h[2], h[3]) << 32) | (u64)packbf(h[0], h[1]);
    g_wbl[i] = ((u64)packbf(__float2bfloat16(l[2]), __float2bfloat16(l[3])) << 32)
             | (u64)packbf(__float2bfloat16(l[0]), __float2bfloat16(l[1]));
}

// -------------------------------------------------------------------------
// Tensor-core projection. ldmatrix A-frags + software-pipelined W LDGs.
// -------------------------------------------------------------------------
#define XSTR 296
#define PSM ((64*XSTR*2 + 2*2048) * 2)

__global__ void __launch_bounds__(256) proj_mma(const float* __restrict__ x) {
    extern __shared__ __nv_bfloat16 psm[];
    __nv_bfloat16* xhi = psm;
    __nv_bfloat16* vsh = psm + 128 * XSTR;
    __nv_bfloat16* vsl = psm + 128 * XSTR + 2048;

    int tid = threadIdx.x;
    int row0 = blockIdx.x * 64;

    // ---- load x, convert to bf16 hi/lo ----
    {
        const float4* xg = (const float4*)(x + (size_t)row0 * CC);
        for (int i = tid; i < 64 * 72; i += 256) {
            int row = i / 72, c4 = i % 72;
            float4 v = xg[i];
            __nv_bfloat16 h0 = __float2bfloat16(v.x), h1 = __float2bfloat16(v.y);
            __nv_bfloat16 h2 = __float2bfloat16(v.z), h3 = __float2bfloat16(v.w);
            *(uint2*)(xhi + row * XSTR + c4 * 4) =
                make_uint2(packbf(h0, h1), packbf(h2, h3));
            *(uint2*)(xhi + (64 + row) * XSTR + c4 * 4) = make_uint2(
                packbf(__float2bfloat16(v.x - __bfloat162float(h0)),
                       __float2bfloat16(v.y - __bfloat162float(h1))),
                packbf(__float2bfloat16(v.z - __bfloat162float(h2)),
                       __float2bfloat16(v.w - __bfloat162float(h3))));
        }
    }
    __syncthreads();

    int wid = tid >> 5, lane = tid & 31;
    int g = lane >> 2, tig = lane & 3;
    int rs = wid & 3, half = wid >> 2;
    int lr = lane & 7, lm = lane >> 3;

    // ldmatrix per-lane bases for A frags (hi at rows 0-63, lo at rows 64-127)
    u32 smb = smem_u32(psm);
    u32 xh_b = smb + (u32)(((rs * 16 + lr + (lm & 1) * 8) * XSTR + (lm >> 1) * 8) * 2);
    u32 xl_b = xh_b + (u32)(64 * XSTR * 2);

    // per-unit W index bases
    int ou[6];
#pragma unroll
    for (int u = 0; u < 6; u++) {
        int idx = half * 6 + u;
        int p = idx >> 2, nt = idx & 3;
        ou[u] = ((p * NKS) * 32 + nt * 8 + g) * 4 + tig;
    }

    float oacc[6][4];
#pragma unroll
    for (int u = 0; u < 6; u++)
#pragma unroll
        for (int j = 0; j < 4; j++) oacc[u][j] = 0.f;

    u64 wh[6], wl[6];
#pragma unroll
    for (int u = 0; u < 6; u++) { wh[u] = g_wbh[ou[u]]; wl[u] = g_wbl[ou[u]]; }

    for (int ks = 0; ks < NKS; ks++) {
        u64 nwh[6], nwl[6];
        if (ks + 1 < NKS) {
            int o2 = (ks + 1) * 128;
#pragma unroll
            for (int u = 0; u < 6; u++) { nwh[u] = g_wbh[ou[u] + o2]; nwl[u] = g_wbl[ou[u] + o2]; }
        }
        u32 ah[4], al[4];
        ldsm4(ah[0], ah[1], ah[2], ah[3], xh_b + (u32)(ks * 32));
        ldsm4(al[0], al[1], al[2], al[3], xl_b + (u32)(ks * 32));
#pragma unroll
        for (int u = 0; u < 6; u++) {
            u32 bh[2] = { (u32)wh[u], (u32)(wh[u] >> 32) };
            u32 bl[2] = { (u32)wl[u], (u32)(wl[u] >> 32) };
            mma_bf16(oacc[u], ah, bh);   // hi*hi
            mma_bf16(oacc[u], al, bh);   // lo*hi
            mma_bf16(oacc[u], ah, bl);   // hi*lo
        }
        if (ks + 1 < NKS) {
#pragma unroll
            for (int u = 0; u < 6; u++) { wh[u] = nwh[u]; wl[u] = nwl[u]; }
        }
    }

    // ---- write K/Q split rows; stage V transposed ----
#pragma unroll
    for (int u = 0; u < 6; u++) {
        int idx = half * 6 + u;
        int p = idx >> 2, nt = idx & 3;
        int c0 = nt * 8 + 2 * tig;
        int rloc0 = rs * 16 + g;
#pragma unroll
        for (int rr = 0; rr < 2; rr++) {
            int rloc = rloc0 + rr * 8;
            float v0 = oacc[u][rr * 2], v1 = oacc[u][rr * 2 + 1];
            __nv_bfloat16 h0 = __float2bfloat16(v0), h1 = __float2bfloat16(v1);
            u32 hp = packbf(h0, h1);
            u32 lp = packbf(__float2bfloat16(v0 - __bfloat162float(h0)),
                            __float2bfloat16(v1 - __bfloat162float(h1)));
            if (p == 0) {
                size_t r = (size_t)(row0 + rloc) * 64;
                *(u32*)(g_kspl + r + c0) = hp;
                *(u32*)(g_kspl + r + 32 + c0) = lp;
            } else if (p == 1) {
                size_t r = (size_t)(row0 + rloc) * 64;
                *(u32*)(g_qspl + r + c0) = hp;
                *(u32*)(g_qspl + r + 32 + c0) = lp;
            } else {
                vsh[c0 * 64 + rloc] = h0;
                vsh[(c0 + 1) * 64 + rloc] = h1;
                vsl[c0 * 64 + rloc] = __ushort_as_bfloat16((unsigned short)(lp & 0xffff));
                vsl[(c0 + 1) * 64 + rloc] = __ushort_as_bfloat16((unsigned short)(lp >> 16));
            }
        }
    }
    __syncthreads();
    {
        int b = row0 >> 11, tin = row0 & (TT - 1);
        int h = tid >> 3, seg = tid & 7;
        size_t gb = ((size_t)(b * HS + h)) * TT + tin + seg * 8;
        *(uint4*)(g_vth + gb) = *(const uint4*)(vsh + h * 64 + seg * 8);
        *(uint4*)(g_vtl + gb) = *(const uint4*)(vsl + h * 64 + seg * 8);
    }
}

// -------------------------------------------------------------------------
// Flash attention on mma.sync: ldmatrix fragment loads + packed epilogue.
// -------------------------------------------------------------------------
#define KSTR 72
#define VSTR 136
#define SMEMB ((256*KSTR + 64*VSTR) * 2)

__global__ void __launch_bounds__(256) attn_mma(float* __restrict__ out) {
    extern __shared__ __nv_bfloat16 sm[];
    __nv_bfloat16* ks  = sm;
    __nv_bfloat16* qs  = sm + 128 * KSTR;
    __nv_bfloat16* vhs = sm + 256 * KSTR;
    __nv_bfloat16* vls = sm + 256 * KSTR + 32 * VSTR;

    int tid = threadIdx.x, wid = tid >> 5, lane = tid & 31;
    int qr = lane >> 2, qc = (lane & 3) << 1;
    int lr = lane & 7, lm = lane >> 3;
    int tile = 15 - (int)(blockIdx.x >> 4);     // longest first
    int b = blockIdx.x & 15;
    int t0 = tile << 7;
    int r1 = (wid << 4) + qr;
    int trow1 = t0 + r1, trow2 = trow1 + 8;

    // ldmatrix per-lane bases
    u32 smb = smem_u32(sm);
    u32 qs_a  = smb + 128 * KSTR * 2;
    u32 vhs_a = smb + 256 * KSTR * 2;
    u32 vls_a = vhs_a + 32 * VSTR * 2;
    u32 qcol2 = (lm == 0) ? 0u : (lm == 1) ? 16u : (lm == 2) ? 64u : 80u;
    u32 qlb = qs_a + (u32)(lr * KSTR * 2) + qcol2;
    u32 vlb = ((lm & 2) ? vls_a : vhs_a) + (u32)(lr * VSTR * 2) + (u32)((lm & 1) * 16);

    // ---- K tile: global -> padded smem (once) ----
    {
        const uint4* kg = (const uint4*)(g_kspl + ((size_t)(b * TT + t0)) * 64);
        for (int i = tid; i < 1024; i += 256) {
            int row = i >> 3, seg = i & 7;
            *(uint4*)(ks + row * KSTR + seg * 8) = kg[row * 8 + seg];
        }
    }
    __syncthreads();

    u32 aK[2][2][4];
#pragma unroll
    for (int sp = 0; sp < 2; sp++)
#pragma unroll
        for (int kk = 0; kk < 2; kk++) {
            int c = sp * 32 + kk * 16 + qc;
            aK[sp][kk][0] = *(const u32*)(ks + r1 * KSTR + c);
            aK[sp][kk][1] = *(const u32*)(ks + (r1 + 8) * KSTR + c);
            aK[sp][kk][2] = *(const u32*)(ks + r1 * KSTR + c + 8);
            aK[sp][kk][3] = *(const u32*)(ks + (r1 + 8) * KSTR + c + 8);
        }

    float oacc[4][4];
#pragma unroll
    for (int i = 0; i < 4; i++)
#pragma unroll
        for (int j = 0; j < 4; j++) oacc[i][j] = 0.f;
    float den1 = 0.f, den2 = 0.f;

    for (int st = 0; st <= tile; st++) {
        int s0 = st << 7;
        __syncthreads();
        {
            const uint4* qg = (const uint4*)(g_qspl + ((size_t)(b * TT + s0)) * 64);
            for (int i = tid; i < 1024; i += 256) {
                int row = i >> 3, seg = i & 7;
                *(uint4*)(qs + row * KSTR + seg * 8) = qg[row * 8 + seg];
            }
        }
        for (int i = tid; i < 512; i += 256) {
            int row = i >> 4, seg = i & 15;
            size_t base = ((size_t)(b * HS + row)) * TT + s0;
            *(uint4*)(vhs + row * VSTR + seg * 8) = *((const uint4*)(g_vth + base) + seg);
            *(uint4*)(vls + row * VSTR + seg * 8) = *((const uint4*)(g_vtl + base) + seg);
        }
        __syncthreads();

        bool diag = (st == tile);
#pragma unroll 1
        for (int ch = 0; ch < 4; ch++) {
            // ---- S = K.Q^T ----
            float sacc[4][4];
#pragma unroll
            for (int i = 0; i < 4; i++)
#pragma unroll
                for (int j = 0; j < 4; j++) sacc[i][j] = 0.f;
#pragma unroll
            for (int kk = 0; kk < 2; kk++) {
#pragma unroll
                for (int nt = 0; nt < 4; nt++) {
                    u32 b0, b1, b2, b3;
                    ldsm4(b0, b1, b2, b3,
                          qlb + (u32)((((ch * 32 + nt * 8) * KSTR) + kk * 16) * 2));
                    u32 bh[2] = { b0, b1 }, bl[2] = { b2, b3 };
                    mma_bf16(sacc[nt], aK[0][kk], bh);
                    mma_bf16(sacc[nt], aK[1][kk], bh);
                    mma_bf16(sacc[nt], aK[0][kk], bl);
                }
            }
            // ---- packed exp epilogue -> P fragments ----
            u32 pha[2][4], pla[2][4];
            int scb = s0 + ch * 32;
#pragma unroll
            for (int nt = 0; nt < 4; nt++) {
                int c0 = scb + nt * 8 + qc;
                float p0, p1, p2, p3;
                if (diag) {
                    p0 = (c0     <= trow1) ? __expf(sacc[nt][0]) : 0.f;
                    p1 = (c0 + 1 <= trow1) ? __expf(sacc[nt][1]) : 0.f;
                    p2 = (c0     <= trow2) ? __expf(sacc[nt][2]) : 0.f;
                    p3 = (c0 + 1 <= trow2) ? __expf(sacc[nt][3]) : 0.f;
                } else {
                    p0 = __expf(sacc[nt][0]);
                    p1 = __expf(sacc[nt][1]);
                    p2 = __expf(sacc[nt][2]);
                    p3 = __expf(sacc[nt][3]);
                }
                den1 += p0 + p1;
                den2 += p2 + p3;
                u32 hp01 = cvt2bf(p1, p0);
                u32 hp23 = cvt2bf(p3, p2);
                float h0 = __uint_as_float(hp01 << 16);
                float h1 = __uint_as_float(hp01 & 0xffff0000u);
                float h2 = __uint_as_float(hp23 << 16);
                float h3 = __uint_as_float(hp23 & 0xffff0000u);
                u32 lp01 = cvt2bf(p1 - h1, p0 - h0);
                u32 lp23 = cvt2bf(p3 - h3, p2 - h2);
                int j = nt >> 1, o = (nt & 1) << 1;
                pha[j][o] = hp01; pha[j][o + 1] = hp23;
                pla[j][o] = lp01; pla[j][o + 1] = lp23;
            }
            // ---- O += P.V ----
#pragma unroll
            for (int j = 0; j < 2; j++) {
#pragma unroll
                for (int hnt = 0; hnt < 4; hnt++) {
                    u32 b0, b1, b2, b3;
                    ldsm4(b0, b1, b2, b3,
                          vlb + (u32)((hnt * 8 * VSTR + ch * 32 + j * 16) * 2));
                    u32 bvh[2] = { b0, b1 }, bvl[2] = { b2, b3 };
                    mma_bf16(oacc[hnt], pha[j], bvh);
                    mma_bf16(oacc[hnt], pla[j], bvh);
                    mma_bf16(oacc[hnt], pha[j], bvl);
                }
            }
        }
    }

    den1 += __shfl_xor_sync(0xffffffffu, den1, 1);
    den1 += __shfl_xor_sync(0xffffffffu, den1, 2);
    den2 += __shfl_xor_sync(0xffffffffu, den2, 1);
    den2 += __shfl_xor_sync(0xffffffffu, den2, 2);
    float rinv1 = 1.f / den1, rinv2 = 1.f / den2;

    float* o1 = out + ((size_t)(b * TT + trow1)) * HS;
    float* o2 = out + ((size_t)(b * TT + trow2)) * HS;
#pragma unroll
    for (int hnt = 0; hnt < 4; hnt++) {
        int col = hnt * 8 + qc;
        *(float2*)(o1 + col) = make_float2(oacc[hnt][0] * rinv1, oacc[hnt][1] * rinv1);
        *(float2*)(o2 + col) = make_float2(oacc[hnt][2] * rinv2, oacc[hnt][3] * rinv2);
    }
}

extern "C" void kernel_launch(void* const* d_in, const int* in_sizes, int n_in,
                              void* d_out, int out_size) {
    const float* x  = (const float*)d_in[0];
    const float* Wk = (const float*)d_in[1];
    const float* Wq = (const float*)d_in[2];
    const float* Wv = (const float*)d_in[3];
    float* out = (float*)d_out;

    prepack_kernel<<<(3 * NKS * 32 * 4 + 255) / 256, 256>>>(Wk, Wq, Wv);

    cudaFuncSetAttribute(proj_mma, cudaFuncAttributeMaxDynamicSharedMemorySize, PSM);
    proj_mma<<<NROWS / 64, 256, PSM>>>(x);

    cudaFuncSetAttribute(attn_mma, cudaFuncAttributeMaxDynamicSharedMemorySize, SMEMB);
    attn_mma<<<256, 256, SMEMB>>>(out);
}

// round 10
// speedup vs baseline: 2.3384x; 1.3338x over previous
#include <cuda_runtime.h>
#include <cuda_bf16.h>

#define BB 16
#define TT 2048
#define CC 288
#define HS 32
#define NROWS (BB*TT)
#define NKS (CC/16)
#define QKSCALE 0.17677669529663687f

typedef unsigned long long u64;
typedef unsigned int u32;

// ---- scratch (device globals; cudaMalloc forbidden) ----
__device__ __align__(16) __nv_bfloat16 g_kspl[NROWS*64];
__device__ __align__(16) __nv_bfloat16 g_qspl[NROWS*64];
__device__ __align__(16) __nv_bfloat16 g_vth[BB*HS*TT];
__device__ __align__(16) __nv_bfloat16 g_vtl[BB*HS*TT];
__device__ u64 g_wbh[3*NKS*32*4];
__device__ u64 g_wbl[3*NKS*32*4];
__device__ float g_pacc[(size_t)4*NROWS*HS];   // split-s partial P.V
__device__ float g_pden[4*NROWS];              // split-s partial sum(exp)

__device__ __forceinline__ u32 packbf(__nv_bfloat16 a, __nv_bfloat16 b) {
    return ((u32)__bfloat16_as_ushort(b) << 16) | (u32)__bfloat16_as_ushort(a);
}
__device__ __forceinline__ u32 smem_u32(const void* p) {
    u32 a; asm("{ .reg .u64 t; cvta.to.shared.u64 t, %1; cvt.u32.u64 %0, t; }" : "=r"(a) : "l"(p));
    return a;
}
__device__ __forceinline__ u32 cvt2bf(float hi, float lo) {
    u32 r; asm("cvt.rn.bf16x2.f32 %0,%1,%2;" : "=r"(r) : "f"(hi), "f"(lo)); return r;
}
__device__ __forceinline__ void mma_bf16(float* d, const u32* a, const u32* b) {
    asm volatile(
        "mma.sync.aligned.m16n8k16.row.col.f32.bf16.bf16.f32 "
        "{%0,%1,%2,%3}, {%4,%5,%6,%7}, {%8,%9}, {%0,%1,%2,%3};"
        : "+f"(d[0]), "+f"(d[1]), "+f"(d[2]), "+f"(d[3])
        : "r"(a[0]), "r"(a[1]), "r"(a[2]), "r"(a[3]), "r"(b[0]), "r"(b[1]));
}
__device__ __forceinline__ void ldsm4(u32& r0, u32& r1, u32& r2, u32& r3, u32 addr) {
    asm volatile("ldmatrix.sync.aligned.m8n8.x4.shared.b16 {%0,%1,%2,%3}, [%4];"
                 : "=r"(r0), "=r"(r1), "=r"(r2), "=r"(r3) : "r"(addr));
}

// ---- (tile, chunk<<8) worklist: heavy chunks (4 s-tiles) first ----
static __device__ const int g_pairs[40] = {
    15, 15|256, 15|512, 15|768,
    14, 14|256, 14|512,
    13, 13|256, 13|512,
    12, 12|256, 12|512,
    11, 11|256, 11|512,
    10, 10|256, 9, 9|256, 8, 8|256, 7, 7|256,
    6, 5, 4, 3,
    14|768, 10|512, 6|256, 2,      // 3-unit
    13|768, 9|512, 5|256, 1,       // 2-unit
    12|768, 8|512, 4|256, 0        // 1-unit
};

// -------------------------------------------------------------------------
// Prepack: W -> bf16 hi/lo B-fragment u64s, QKSCALE folded into Wk.
// -------------------------------------------------------------------------
__global__ void prepack_kernel(const float* __restrict__ Wk,
                               const float* __restrict__ Wq,
                               const float* __restrict__ Wv) {
    int i = blockIdx.x * 256 + threadIdx.x;
    if (i >= 3 * NKS * 32 * 4) return;
    int tig = i & 3;
    int n = (i >> 2) & 31;
    int ks = (i >> 7) % NKS;
    int p = i / (NKS * 32 * 4);
    const float* W = (p == 0) ? Wk : (p == 1) ? Wq : Wv;
    float s = (p == 0) ? QKSCALE : 1.0f;
    int c0 = ks * 16 + tig * 2;
    float w[4];
    w[0] = W[(c0)     * HS + n] * s;
    w[1] = W[(c0 + 1) * HS + n] * s;
    w[2] = W[(c0 + 8) * HS + n] * s;
    w[3] = W[(c0 + 9) * HS + n] * s;
    __nv_bfloat16 h[4]; float l[4];
#pragma unroll
    for (int j = 0; j < 4; j++) { h[j] = __float2bfloat16(w[j]); l[j] = w[j] - __bfloat162float(h[j]); }
    g_wbh[i] = ((u64)packbf(h[2], h[3]) << 32) | (u64)packbf(h[0], h[1]);
    g_wbl[i] = ((u64)packbf(__float2bfloat16(l[2]), __float2bfloat16(l[3])) << 32)
             | (u64)packbf(__float2bfloat16(l[0]), __float2bfloat16(l[1]));
}

// -------------------------------------------------------------------------
// Tensor-core projection (unchanged from round 9).
// -------------------------------------------------------------------------
#define XSTR 296
#define PSM ((64*XSTR*2 + 2*2048) * 2)

__global__ void __launch_bounds__(256) proj_mma(const float* __restrict__ x) {
    extern __shared__ __nv_bfloat16 psm[];
    __nv_bfloat16* xhi = psm;
    __nv_bfloat16* vsh = psm + 128 * XSTR;
    __nv_bfloat16* vsl = psm + 128 * XSTR + 2048;

    int tid = threadIdx.x;
    int row0 = blockIdx.x * 64;

    {
        const float4* xg = (const float4*)(x + (size_t)row0 * CC);
        for (int i = tid; i < 64 * 72; i += 256) {
            int row = i / 72, c4 = i % 72;
            float4 v = xg[i];
            __nv_bfloat16 h0 = __float2bfloat16(v.x), h1 = __float2bfloat16(v.y);
            __nv_bfloat16 h2 = __float2bfloat16(v.z), h3 = __float2bfloat16(v.w);
            *(uint2*)(xhi + row * XSTR + c4 * 4) =
                make_uint2(packbf(h0, h1), packbf(h2, h3));
            *(uint2*)(xhi + (64 + row) * XSTR + c4 * 4) = make_uint2(
                packbf(__float2bfloat16(v.x - __bfloat162float(h0)),
                       __float2bfloat16(v.y - __bfloat162float(h1))),
                packbf(__float2bfloat16(v.z - __bfloat162float(h2)),
                       __float2bfloat16(v.w - __bfloat162float(h3))));
        }
    }
    __syncthreads();

    int wid = tid >> 5, lane = tid & 31;
    int g = lane >> 2, tig = lane & 3;
    int rs = wid & 3, half = wid >> 2;
    int lr = lane & 7, lm = lane >> 3;

    u32 smb = smem_u32(psm);
    u32 xh_b = smb + (u32)(((rs * 16 + lr + (lm & 1) * 8) * XSTR + (lm >> 1) * 8) * 2);
    u32 xl_b = xh_b + (u32)(64 * XSTR * 2);

    int ou[6];
#pragma unroll
    for (int u = 0; u < 6; u++) {
        int idx = half * 6 + u;
        int p = idx >> 2, nt = idx & 3;
        ou[u] = ((p * NKS) * 32 + nt * 8 + g) * 4 + tig;
    }

    float oacc[6][4];
#pragma unroll
    for (int u = 0; u < 6; u++)
#pragma unroll
        for (int j = 0; j < 4; j++) oacc[u][j] = 0.f;

    u64 wh[6], wl[6];
#pragma unroll
    for (int u = 0; u < 6; u++) { wh[u] = g_wbh[ou[u]]; wl[u] = g_wbl[ou[u]]; }

    for (int ks = 0; ks < NKS; ks++) {
        u64 nwh[6], nwl[6];
        if (ks + 1 < NKS) {
            int o2 = (ks + 1) * 128;
#pragma unroll
            for (int u = 0; u < 6; u++) { nwh[u] = g_wbh[ou[u] + o2]; nwl[u] = g_wbl[ou[u] + o2]; }
        }
        u32 ah[4], al[4];
        ldsm4(ah[0], ah[1], ah[2], ah[3], xh_b + (u32)(ks * 32));
        ldsm4(al[0], al[1], al[2], al[3], xl_b + (u32)(ks * 32));
#pragma unroll
        for (int u = 0; u < 6; u++) {
            u32 bh[2] = { (u32)wh[u], (u32)(wh[u] >> 32) };
            u32 bl[2] = { (u32)wl[u], (u32)(wl[u] >> 32) };
            mma_bf16(oacc[u], ah, bh);
            mma_bf16(oacc[u], al, bh);
            mma_bf16(oacc[u], ah, bl);
        }
        if (ks + 1 < NKS) {
#pragma unroll
            for (int u = 0; u < 6; u++) { wh[u] = nwh[u]; wl[u] = nwl[u]; }
        }
    }

#pragma unroll
    for (int u = 0; u < 6; u++) {
        int idx = half * 6 + u;
        int p = idx >> 2, nt = idx & 3;
        int c0 = nt * 8 + 2 * tig;
        int rloc0 = rs * 16 + g;
#pragma unroll
        for (int rr = 0; rr < 2; rr++) {
            int rloc = rloc0 + rr * 8;
            float v0 = oacc[u][rr * 2], v1 = oacc[u][rr * 2 + 1];
            __nv_bfloat16 h0 = __float2bfloat16(v0), h1 = __float2bfloat16(v1);
            u32 hp = packbf(h0, h1);
            u32 lp = packbf(__float2bfloat16(v0 - __bfloat162float(h0)),
                            __float2bfloat16(v1 - __bfloat162float(h1)));
            if (p == 0) {
                size_t r = (size_t)(row0 + rloc) * 64;
                *(u32*)(g_kspl + r + c0) = hp;
                *(u32*)(g_kspl + r + 32 + c0) = lp;
            } else if (p == 1) {
                size_t r = (size_t)(row0 + rloc) * 64;
                *(u32*)(g_qspl + r + c0) = hp;
                *(u32*)(g_qspl + r + 32 + c0) = lp;
            } else {
                vsh[c0 * 64 + rloc] = h0;
                vsh[(c0 + 1) * 64 + rloc] = h1;
                vsl[c0 * 64 + rloc] = __ushort_as_bfloat16((unsigned short)(lp & 0xffff));
                vsl[(c0 + 1) * 64 + rloc] = __ushort_as_bfloat16((unsigned short)(lp >> 16));
            }
        }
    }
    __syncthreads();
    {
        int b = row0 >> 11, tin = row0 & (TT - 1);
        int h = tid >> 3, seg = tid & 7;
        size_t gb = ((size_t)(b * HS + h)) * TT + tin + seg * 8;
        *(uint4*)(g_vth + gb) = *(const uint4*)(vsh + h * 64 + seg * 8);
        *(uint4*)(g_vtl + gb) = *(const uint4*)(vsl + h * 64 + seg * 8);
    }
}

// -------------------------------------------------------------------------
// Flash attention, split-s over chunks of <=4 s-tiles. Partials additive
// (no max-rescale; scores O(5), fp32-safe). Compute per unit identical to
// the passing round-9 kernel.
// -------------------------------------------------------------------------
#define KSTR 72
#define VSTR 136
#define SMEMB ((256*KSTR + 64*VSTR) * 2)

__global__ void __launch_bounds__(256) attn_mma() {
    extern __shared__ __nv_bfloat16 sm[];
    __nv_bfloat16* ks  = sm;
    __nv_bfloat16* qs  = sm + 128 * KSTR;
    __nv_bfloat16* vhs = sm + 256 * KSTR;
    __nv_bfloat16* vls = sm + 256 * KSTR + 32 * VSTR;

    int pr = g_pairs[blockIdx.x];
    int tile = pr & 0xff;
    int slot = pr >> 8;                 // chunk index within tile (0..3)
    int b = blockIdx.y;

    int tid = threadIdx.x, wid = tid >> 5, lane = tid & 31;
    int qr = lane >> 2, qc = (lane & 3) << 1;
    int lr = lane & 7, lm = lane >> 3;
    int t0 = tile << 7;
    int r1 = (wid << 4) + qr;
    int trow1 = t0 + r1, trow2 = trow1 + 8;

    u32 smb = smem_u32(sm);
    u32 qs_a  = smb + 128 * KSTR * 2;
    u32 vhs_a = smb + 256 * KSTR * 2;
    u32 vls_a = vhs_a + 32 * VSTR * 2;
    u32 qcol2 = (lm == 0) ? 0u : (lm == 1) ? 16u : (lm == 2) ? 64u : 80u;
    u32 qlb = qs_a + (u32)(lr * KSTR * 2) + qcol2;
    u32 vlb = ((lm & 2) ? vls_a : vhs_a) + (u32)(lr * VSTR * 2) + (u32)((lm & 1) * 16);

    // ---- K tile (once per block) ----
    {
        const uint4* kg = (const uint4*)(g_kspl + ((size_t)(b * TT + t0)) * 64);
        for (int i = tid; i < 1024; i += 256) {
            int row = i >> 3, seg = i & 7;
            *(uint4*)(ks + row * KSTR + seg * 8) = kg[row * 8 + seg];
        }
    }
    __syncthreads();

    u32 aK[2][2][4];
#pragma unroll
    for (int sp = 0; sp < 2; sp++)
#pragma unroll
        for (int kk = 0; kk < 2; kk++) {
            int c = sp * 32 + kk * 16 + qc;
            aK[sp][kk][0] = *(const u32*)(ks + r1 * KSTR + c);
            aK[sp][kk][1] = *(const u32*)(ks + (r1 + 8) * KSTR + c);
            aK[sp][kk][2] = *(const u32*)(ks + r1 * KSTR + c + 8);
            aK[sp][kk][3] = *(const u32*)(ks + (r1 + 8) * KSTR + c + 8);
        }

    float oacc[4][4];
#pragma unroll
    for (int i = 0; i < 4; i++)
#pragma unroll
        for (int j = 0; j < 4; j++) oacc[i][j] = 0.f;
    float den1 = 0.f, den2 = 0.f;

    int st_beg = slot * 4;
    int st_end = st_beg + 4;
    if (st_end > tile + 1) st_end = tile + 1;

    for (int st = st_beg; st < st_end; st++) {
        int s0 = st << 7;
        __syncthreads();
        {
            const uint4* qg = (const uint4*)(g_qspl + ((size_t)(b * TT + s0)) * 64);
            for (int i = tid; i < 1024; i += 256) {
                int row = i >> 3, seg = i & 7;
                *(uint4*)(qs + row * KSTR + seg * 8) = qg[row * 8 + seg];
            }
        }
        for (int i = tid; i < 512; i += 256) {
            int row = i >> 4, seg = i & 15;
            size_t base = ((size_t)(b * HS + row)) * TT + s0;
            *(uint4*)(vhs + row * VSTR + seg * 8) = *((const uint4*)(g_vth + base) + seg);
            *(uint4*)(vls + row * VSTR + seg * 8) = *((const uint4*)(g_vtl + base) + seg);
        }
        __syncthreads();

        bool diag = (st == tile);
#pragma unroll 1
        for (int ch = 0; ch < 4; ch++) {
            float sacc[4][4];
#pragma unroll
            for (int i = 0; i < 4; i++)
#pragma unroll
                for (int j = 0; j < 4; j++) sacc[i][j] = 0.f;
#pragma unroll
            for (int kk = 0; kk < 2; kk++) {
#pragma unroll
                for (int nt = 0; nt < 4; nt++) {
                    u32 b0, b1, b2, b3;
                    ldsm4(b0, b1, b2, b3,
                          qlb + (u32)((((ch * 32 + nt * 8) * KSTR) + kk * 16) * 2));
                    u32 bh[2] = { b0, b1 }, bl[2] = { b2, b3 };
                    mma_bf16(sacc[nt], aK[0][kk], bh);
                    mma_bf16(sacc[nt], aK[1][kk], bh);
                    mma_bf16(sacc[nt], aK[0][kk], bl);
                }
            }
            u32 pha[2][4], pla[2][4];
            int scb = (st << 7) + ch * 32;
#pragma unroll
            for (int nt = 0; nt < 4; nt++) {
                int c0 = scb + nt * 8 + qc;
                float p0, p1, p2, p3;
                if (diag) {
                    p0 = (c0     <= trow1) ? __expf(sacc[nt][0]) : 0.f;
                    p1 = (c0 + 1 <= trow1) ? __expf(sacc[nt][1]) : 0.f;
                    p2 = (c0     <= trow2) ? __expf(sacc[nt][2]) : 0.f;
                    p3 = (c0 + 1 <= trow2) ? __expf(sacc[nt][3]) : 0.f;
                } else {
                    p0 = __expf(sacc[nt][0]);
                    p1 = __expf(sacc[nt][1]);
                    p2 = __expf(sacc[nt][2]);
                    p3 = __expf(sacc[nt][3]);
                }
                den1 += p0 + p1;
                den2 += p2 + p3;
                u32 hp01 = cvt2bf(p1, p0);
                u32 hp23 = cvt2bf(p3, p2);
                float h0 = __uint_as_float(hp01 << 16);
                float h1 = __uint_as_float(hp01 & 0xffff0000u);
                float h2 = __uint_as_float(hp23 << 16);
                float h3 = __uint_as_float(hp23 & 0xffff0000u);
                u32 lp01 = cvt2bf(p1 - h1, p0 - h0);
                u32 lp23 = cvt2bf(p3 - h3, p2 - h2);
                int j = nt >> 1, o = (nt & 1) << 1;
                pha[j][o] = hp01; pha[j][o + 1] = hp23;
                pla[j][o] = lp01; pla[j][o + 1] = lp23;
            }
#pragma unroll
            for (int j = 0; j < 2; j++) {
#pragma unroll
                for (int hnt = 0; hnt < 4; hnt++) {
                    u32 b0, b1, b2, b3;
                    ldsm4(b0, b1, b2, b3,
                          vlb + (u32)((hnt * 8 * VSTR + ch * 32 + j * 16) * 2));
                    u32 bvh[2] = { b0, b1 }, bvl[2] = { b2, b3 };
                    mma_bf16(oacc[hnt], pha[j], bvh);
                    mma_bf16(oacc[hnt], pla[j], bvh);
                    mma_bf16(oacc[hnt], pha[j], bvl);
                }
            }
        }
    }

    den1 += __shfl_xor_sync(0xffffffffu, den1, 1);
    den1 += __shfl_xor_sync(0xffffffffu, den1, 2);
    den2 += __shfl_xor_sync(0xffffffffu, den2, 1);
    den2 += __shfl_xor_sync(0xffffffffu, den2, 2);

    size_t r1g = (size_t)b * TT + trow1;
    size_t r2g = (size_t)b * TT + trow2;
    float* pa = g_pacc + ((size_t)slot * NROWS + r1g) * HS;
    float* pb = g_pacc + ((size_t)slot * NROWS + r2g) * HS;
#pragma unroll
    for (int hnt = 0; hnt < 4; hnt++) {
        int col = hnt * 8 + qc;
        *(float2*)(pa + col) = make_float2(oacc[hnt][0], oacc[hnt][1]);
        *(float2*)(pb + col) = make_float2(oacc[hnt][2], oacc[hnt][3]);
    }
    if ((lane & 3) == 0) {
        g_pden[slot * NROWS + r1g] = den1;
        g_pden[slot * NROWS + r2g] = den2;
    }
}

// -------------------------------------------------------------------------
// Combine split-s partials and normalize. One float4 per thread.
// -------------------------------------------------------------------------
__global__ void combine_kernel(float* __restrict__ out) {
    int gid = blockIdx.x * 256 + threadIdx.x;     // NROWS*8 threads
    int row = gid >> 3;
    int q = gid & 7;
    int t = row & (TT - 1);
    int cmax = (t >> 7) >> 2;                     // chunks-1 for this row's tile
    float4 a = make_float4(0.f, 0.f, 0.f, 0.f);
    float den = 0.f;
    const float4* pacc4 = (const float4*)g_pacc;
    for (int c = 0; c <= cmax; c++) {
        den += g_pden[c * NROWS + row];
        float4 v = pacc4[((size_t)c * NROWS + row) * 8 + q];
        a.x += v.x; a.y += v.y; a.z += v.z; a.w += v.w;
    }
    float rinv = 1.f / den;
    ((float4*)out)[(size_t)row * 8 + q] =
        make_float4(a.x * rinv, a.y * rinv, a.z * rinv, a.w * rinv);
}

extern "C" void kernel_launch(void* const* d_in, const int* in_sizes, int n_in,
                              void* d_out, int out_size) {
    const float* x  = (const float*)d_in[0];
    const float* Wk = (const float*)d_in[1];
    const float* Wq = (const float*)d_in[2];
    const float* Wv = (const float*)d_in[3];
    float* out = (float*)d_out;

    prepack_kernel<<<(3 * NKS * 32 * 4 + 255) / 256, 256>>>(Wk, Wq, Wv);

    cudaFuncSetAttribute(proj_mma, cudaFuncAttributeMaxDynamicSharedMemorySize, PSM);
    proj_mma<<<NROWS / 64, 256, PSM>>>(x);

    cudaFuncSetAttribute(attn_mma, cudaFuncAttributeMaxDynamicSharedMemorySize, SMEMB);
    dim3 ag(40, BB);
    attn_mma<<<ag, 256, SMEMB>>>();

    combine_kernel<<<NROWS * 8 / 256, 256>>>(out);
}

// round 11
// speedup vs baseline: 2.4389x; 1.0430x over previous
#include <cuda_runtime.h>
#include <cuda_bf16.h>

#define BB 16
#define TT 2048
#define CC 288
#define HS 32
#define NROWS (BB*TT)
#define NKS (CC/16)
#define QKSCALE 0.17677669529663687f

typedef unsigned long long u64;
typedef unsigned int u32;

// ---- scratch (device globals; cudaMalloc forbidden) ----
__device__ __align__(16) __nv_bfloat16 g_kspl[NROWS*64];
__device__ __align__(16) __nv_bfloat16 g_qspl[NROWS*64];
__device__ __align__(16) __nv_bfloat16 g_vth[BB*HS*TT];
__device__ __align__(16) __nv_bfloat16 g_vtl[BB*HS*TT];
__device__ u64 g_wbh[3*NKS*32*4];
__device__ u64 g_wbl[3*NKS*32*4];
__device__ float g_pacc[(size_t)4*NROWS*HS];   // split-s partial P.V
__device__ float g_pden[4*NROWS];              // split-s partial sum(exp)

__device__ __forceinline__ u32 packbf(__nv_bfloat16 a, __nv_bfloat16 b) {
    return ((u32)__bfloat16_as_ushort(b) << 16) | (u32)__bfloat16_as_ushort(a);
}
__device__ __forceinline__ u32 smem_u32(const void* p) {
    u32 a; asm("{ .reg .u64 t; cvta.to.shared.u64 t, %1; cvt.u32.u64 %0, t; }" : "=r"(a) : "l"(p));
    return a;
}
__device__ __forceinline__ u32 cvt2bf(float hi, float lo) {
    u32 r; asm("cvt.rn.bf16x2.f32 %0,%1,%2;" : "=r"(r) : "f"(hi), "f"(lo)); return r;
}
__device__ __forceinline__ void mma_bf16(float* d, const u32* a, const u32* b) {
    asm volatile(
        "mma.sync.aligned.m16n8k16.row.col.f32.bf16.bf16.f32 "
        "{%0,%1,%2,%3}, {%4,%5,%6,%7}, {%8,%9}, {%0,%1,%2,%3};"
        : "+f"(d[0]), "+f"(d[1]), "+f"(d[2]), "+f"(d[3])
        : "r"(a[0]), "r"(a[1]), "r"(a[2]), "r"(a[3]), "r"(b[0]), "r"(b[1]));
}
__device__ __forceinline__ void ldsm4(u32& r0, u32& r1, u32& r2, u32& r3, u32 addr) {
    asm volatile("ldmatrix.sync.aligned.m8n8.x4.shared.b16 {%0,%1,%2,%3}, [%4];"
                 : "=r"(r0), "=r"(r1), "=r"(r2), "=r"(r3) : "r"(addr));
}
__device__ __forceinline__ void cpa16(u32 dst, const void* src) {
    asm volatile("cp.async.cg.shared.global [%0], [%1], 16;" :: "r"(dst), "l"(src));
}
#define CPCOMMIT() asm volatile("cp.async.commit_group;" ::: "memory")
#define CPWAIT0()  asm volatile("cp.async.wait_group 0;" ::: "memory")

// ---- (tile, chunk<<8) worklist: heavy chunks (4 s-tiles) first ----
static __device__ const int g_pairs[40] = {
    15, 15|256, 15|512, 15|768,
    14, 14|256, 14|512,
    13, 13|256, 13|512,
    12, 12|256, 12|512,
    11, 11|256, 11|512,
    10, 10|256, 9, 9|256, 8, 8|256, 7, 7|256,
    6, 5, 4, 3,
    14|768, 10|512, 6|256, 2,
    13|768, 9|512, 5|256, 1,
    12|768, 8|512, 4|256, 0
};

// -------------------------------------------------------------------------
// Prepack: W -> bf16 hi/lo B-fragment u64s, QKSCALE folded into Wk.
// -------------------------------------------------------------------------
__global__ void prepack_kernel(const float* __restrict__ Wk,
                               const float* __restrict__ Wq,
                               const float* __restrict__ Wv) {
    int i = blockIdx.x * 256 + threadIdx.x;
    if (i >= 3 * NKS * 32 * 4) return;
    int tig = i & 3;
    int n = (i >> 2) & 31;
    int ks = (i >> 7) % NKS;
    int p = i / (NKS * 32 * 4);
    const float* W = (p == 0) ? Wk : (p == 1) ? Wq : Wv;
    float s = (p == 0) ? QKSCALE : 1.0f;
    int c0 = ks * 16 + tig * 2;
    float w[4];
    w[0] = W[(c0)     * HS + n] * s;
    w[1] = W[(c0 + 1) * HS + n] * s;
    w[2] = W[(c0 + 8) * HS + n] * s;
    w[3] = W[(c0 + 9) * HS + n] * s;
    __nv_bfloat16 h[4]; float l[4];
#pragma unroll
    for (int j = 0; j < 4; j++) { h[j] = __float2bfloat16(w[j]); l[j] = w[j] - __bfloat162float(h[j]); }
    g_wbh[i] = ((u64)packbf(h[2], h[3]) << 32) | (u64)packbf(h[0], h[1]);
    g_wbl[i] = ((u64)packbf(__float2bfloat16(l[2]), __float2bfloat16(l[3])) << 32)
             | (u64)packbf(__float2bfloat16(l[0]), __float2bfloat16(l[1]));
}

// -------------------------------------------------------------------------
// Tensor-core projection (unchanged, passing).
// -------------------------------------------------------------------------
#define XSTR 296
#define PSM ((64*XSTR*2 + 2*2048) * 2)

__global__ void __launch_bounds__(256) proj_mma(const float* __restrict__ x) {
    extern __shared__ __nv_bfloat16 psm[];
    __nv_bfloat16* xhi = psm;
    __nv_bfloat16* vsh = psm + 128 * XSTR;
    __nv_bfloat16* vsl = psm + 128 * XSTR + 2048;

    int tid = threadIdx.x;
    int row0 = blockIdx.x * 64;

    {
        const float4* xg = (const float4*)(x + (size_t)row0 * CC);
        for (int i = tid; i < 64 * 72; i += 256) {
            int row = i / 72, c4 = i % 72;
            float4 v = xg[i];
            __nv_bfloat16 h0 = __float2bfloat16(v.x), h1 = __float2bfloat16(v.y);
            __nv_bfloat16 h2 = __float2bfloat16(v.z), h3 = __float2bfloat16(v.w);
            *(uint2*)(xhi + row * XSTR + c4 * 4) =
                make_uint2(packbf(h0, h1), packbf(h2, h3));
            *(uint2*)(xhi + (64 + row) * XSTR + c4 * 4) = make_uint2(
                packbf(__float2bfloat16(v.x - __bfloat162float(h0)),
                       __float2bfloat16(v.y - __bfloat162float(h1))),
                packbf(__float2bfloat16(v.z - __bfloat162float(h2)),
                       __float2bfloat16(v.w - __bfloat162float(h3))));
        }
    }
    __syncthreads();

    int wid = tid >> 5, lane = tid & 31;
    int g = lane >> 2, tig = lane & 3;
    int rs = wid & 3, half = wid >> 2;
    int lr = lane & 7, lm = lane >> 3;

    u32 smb = smem_u32(psm);
    u32 xh_b = smb + (u32)(((rs * 16 + lr + (lm & 1) * 8) * XSTR + (lm >> 1) * 8) * 2);
    u32 xl_b = xh_b + (u32)(64 * XSTR * 2);

    int ou[6];
#pragma unroll
    for (int u = 0; u < 6; u++) {
        int idx = half * 6 + u;
        int p = idx >> 2, nt = idx & 3;
        ou[u] = ((p * NKS) * 32 + nt * 8 + g) * 4 + tig;
    }

    float oacc[6][4];
#pragma unroll
    for (int u = 0; u < 6; u++)
#pragma unroll
        for (int j = 0; j < 4; j++) oacc[u][j] = 0.f;

    u64 wh[6], wl[6];
#pragma unroll
    for (int u = 0; u < 6; u++) { wh[u] = g_wbh[ou[u]]; wl[u] = g_wbl[ou[u]]; }

    for (int ks = 0; ks < NKS; ks++) {
        u64 nwh[6], nwl[6];
        if (ks + 1 < NKS) {
            int o2 = (ks + 1) * 128;
#pragma unroll
            for (int u = 0; u < 6; u++) { nwh[u] = g_wbh[ou[u] + o2]; nwl[u] = g_wbl[ou[u] + o2]; }
        }
        u32 ah[4], al[4];
        ldsm4(ah[0], ah[1], ah[2], ah[3], xh_b + (u32)(ks * 32));
        ldsm4(al[0], al[1], al[2], al[3], xl_b + (u32)(ks * 32));
#pragma unroll
        for (int u = 0; u < 6; u++) {
            u32 bh[2] = { (u32)wh[u], (u32)(wh[u] >> 32) };
            u32 bl[2] = { (u32)wl[u], (u32)(wl[u] >> 32) };
            mma_bf16(oacc[u], ah, bh);
            mma_bf16(oacc[u], al, bh);
            mma_bf16(oacc[u], ah, bl);
        }
        if (ks + 1 < NKS) {
#pragma unroll
            for (int u = 0; u < 6; u++) { wh[u] = nwh[u]; wl[u] = nwl[u]; }
        }
    }

#pragma unroll
    for (int u = 0; u < 6; u++) {
        int idx = half * 6 + u;
        int p = idx >> 2, nt = idx & 3;
        int c0 = nt * 8 + 2 * tig;
        int rloc0 = rs * 16 + g;
#pragma unroll
        for (int rr = 0; rr < 2; rr++) {
            int rloc = rloc0 + rr * 8;
            float v0 = oacc[u][rr * 2], v1 = oacc[u][rr * 2 + 1];
            __nv_bfloat16 h0 = __float2bfloat16(v0), h1 = __float2bfloat16(v1);
            u32 hp = packbf(h0, h1);
            u32 lp = packbf(__float2bfloat16(v0 - __bfloat162float(h0)),
                            __float2bfloat16(v1 - __bfloat162float(h1)));
            if (p == 0) {
                size_t r = (size_t)(row0 + rloc) * 64;
                *(u32*)(g_kspl + r + c0) = hp;
                *(u32*)(g_kspl + r + 32 + c0) = lp;
            } else if (p == 1) {
                size_t r = (size_t)(row0 + rloc) * 64;
                *(u32*)(g_qspl + r + c0) = hp;
                *(u32*)(g_qspl + r + 32 + c0) = lp;
            } else {
                vsh[c0 * 64 + rloc] = h0;
                vsh[(c0 + 1) * 64 + rloc] = h1;
                vsl[c0 * 64 + rloc] = __ushort_as_bfloat16((unsigned short)(lp & 0xffff));
                vsl[(c0 + 1) * 64 + rloc] = __ushort_as_bfloat16((unsigned short)(lp >> 16));
            }
        }
    }
    __syncthreads();
    {
        int b = row0 >> 11, tin = row0 & (TT - 1);
        int h = tid >> 3, seg = tid & 7;
        size_t gb = ((size_t)(b * HS + h)) * TT + tin + seg * 8;
        *(uint4*)(g_vth + gb) = *(const uint4*)(vsh + h * 64 + seg * 8);
        *(uint4*)(g_vtl + gb) = *(const uint4*)(vsl + h * 64 + seg * 8);
    }
}

// -------------------------------------------------------------------------
// Flash attention, split-s + cp.async double-buffered Q/V tiles.
// smem: [ks 9216][qs0 9216][qs1 9216][vh0 4352|vl0 4352][vh1 4352|vl1 4352]
// -------------------------------------------------------------------------
#define KSTR 72
#define VSTR 136
#define QB0   9216
#define VB0   27648
#define QBSZ  9216
#define VBSZ  8704
#define SMEMB (45056 * 2)

__device__ __forceinline__ void load_tile_async(u32 smb, int buf, int b, int s0, int tid) {
    const uint4* qg = (const uint4*)(g_qspl + ((size_t)(b * TT + s0)) * 64);
    u32 qb = smb + (u32)((QB0 + buf * QBSZ) * 2);
#pragma unroll
    for (int k = 0; k < 4; k++) {
        int i = tid + k * 256;
        int row = i >> 3, seg = i & 7;
        cpa16(qb + (u32)((row * KSTR + seg * 8) * 2), qg + i);
    }
    u32 vhb = smb + (u32)((VB0 + buf * VBSZ) * 2);
    u32 vlb = vhb + (u32)(4352 * 2);
#pragma unroll
    for (int k = 0; k < 2; k++) {
        int i = tid + k * 256;
        int row = i >> 4, seg = i & 15;
        size_t base = ((size_t)(b * HS + row)) * TT + s0;
        u32 off = (u32)((row * VSTR + seg * 8) * 2);
        cpa16(vhb + off, ((const uint4*)(g_vth + base)) + seg);
        cpa16(vlb + off, ((const uint4*)(g_vtl + base)) + seg);
    }
}

__global__ void __launch_bounds__(256) attn_mma() {
    extern __shared__ __nv_bfloat16 sm[];
    __nv_bfloat16* ks = sm;

    int pr = g_pairs[blockIdx.x];
    int tile = pr & 0xff;
    int slot = pr >> 8;
    int b = blockIdx.y;

    int tid = threadIdx.x, wid = tid >> 5, lane = tid & 31;
    int qr = lane >> 2, qc = (lane & 3) << 1;
    int lr = lane & 7, lm = lane >> 3;
    int t0 = tile << 7;
    int r1 = (wid << 4) + qr;
    int trow1 = t0 + r1, trow2 = trow1 + 8;

    u32 smb = smem_u32(sm);
    // per-lane ldmatrix offsets RELATIVE to buffer starts
    u32 qcol2 = (lm == 0) ? 0u : (lm == 1) ? 16u : (lm == 2) ? 64u : 80u;
    u32 qlb_off = (u32)(lr * KSTR * 2) + qcol2;
    u32 vlb_off = ((lm & 2) ? (u32)(4352 * 2) : 0u) + (u32)(lr * VSTR * 2) + (u32)((lm & 1) * 16);

    int st_beg = slot * 4;
    int st_end = st_beg + 4;
    if (st_end > tile + 1) st_end = tile + 1;
    int nst = st_end - st_beg;

    // ---- K tile (once per block) + first Q/V tile async ----
    {
        const uint4* kg = (const uint4*)(g_kspl + ((size_t)(b * TT + t0)) * 64);
        for (int i = tid; i < 1024; i += 256) {
            int row = i >> 3, seg = i & 7;
            *(uint4*)(ks + row * KSTR + seg * 8) = kg[row * 8 + seg];
        }
    }
    load_tile_async(smb, 0, b, st_beg << 7, tid);
    CPCOMMIT();
    __syncthreads();

    u32 aK[2][2][4];
#pragma unroll
    for (int sp = 0; sp < 2; sp++)
#pragma unroll
        for (int kk = 0; kk < 2; kk++) {
            int c = sp * 32 + kk * 16 + qc;
            aK[sp][kk][0] = *(const u32*)(ks + r1 * KSTR + c);
            aK[sp][kk][1] = *(const u32*)(ks + (r1 + 8) * KSTR + c);
            aK[sp][kk][2] = *(const u32*)(ks + r1 * KSTR + c + 8);
            aK[sp][kk][3] = *(const u32*)(ks + (r1 + 8) * KSTR + c + 8);
        }

    float oacc[4][4];
#pragma unroll
    for (int i = 0; i < 4; i++)
#pragma unroll
        for (int j = 0; j < 4; j++) oacc[i][j] = 0.f;
    float den1 = 0.f, den2 = 0.f;

    for (int it = 0; it < nst; it++) {
        int st = st_beg + it;
        int cur = it & 1;
        CPWAIT0();
        __syncthreads();
        if (it + 1 < nst) {
            load_tile_async(smb, cur ^ 1, b, (st + 1) << 7, tid);
            CPCOMMIT();
        }
        u32 qlb = smb + (u32)((QB0 + cur * QBSZ) * 2) + qlb_off;
        u32 vlb = smb + (u32)((VB0 + cur * VBSZ) * 2) + vlb_off;

        bool diag = (st == tile);
#pragma unroll 1
        for (int ch = 0; ch < 4; ch++) {
            float sacc[4][4];
#pragma unroll
            for (int i = 0; i < 4; i++)
#pragma unroll
                for (int j = 0; j < 4; j++) sacc[i][j] = 0.f;
#pragma unroll
            for (int kk = 0; kk < 2; kk++) {
#pragma unroll
                for (int nt = 0; nt < 4; nt++) {
                    u32 b0, b1, b2, b3;
                    ldsm4(b0, b1, b2, b3,
                          qlb + (u32)((((ch * 32 + nt * 8) * KSTR) + kk * 16) * 2));
                    u32 bh[2] = { b0, b1 }, bl[2] = { b2, b3 };
                    mma_bf16(sacc[nt], aK[0][kk], bh);
                    mma_bf16(sacc[nt], aK[1][kk], bh);
                    mma_bf16(sacc[nt], aK[0][kk], bl);
                }
            }
            u32 pha[2][4], pla[2][4];
            int scb = (st << 7) + ch * 32;
#pragma unroll
            for (int nt = 0; nt < 4; nt++) {
                int c0 = scb + nt * 8 + qc;
                float p0, p1, p2, p3;
                if (diag) {
                    p0 = (c0     <= trow1) ? __expf(sacc[nt][0]) : 0.f;
                    p1 = (c0 + 1 <= trow1) ? __expf(sacc[nt][1]) : 0.f;
                    p2 = (c0     <= trow2) ? __expf(sacc[nt][2]) : 0.f;
                    p3 = (c0 + 1 <= trow2) ? __expf(sacc[nt][3]) : 0.f;
                } else {
                    p0 = __expf(sacc[nt][0]);
                    p1 = __expf(sacc[nt][1]);
                    p2 = __expf(sacc[nt][2]);
                    p3 = __expf(sacc[nt][3]);
                }
                den1 += p0 + p1;
                den2 += p2 + p3;
                u32 hp01 = cvt2bf(p1, p0);
                u32 hp23 = cvt2bf(p3, p2);
                float h0 = __uint_as_float(hp01 << 16);
                float h1 = __uint_as_float(hp01 & 0xffff0000u);
                float h2 = __uint_as_float(hp23 << 16);
                float h3 = __uint_as_float(hp23 & 0xffff0000u);
                u32 lp01 = cvt2bf(p1 - h1, p0 - h0);
                u32 lp23 = cvt2bf(p3 - h3, p2 - h2);
                int j = nt >> 1, o = (nt & 1) << 1;
                pha[j][o] = hp01; pha[j][o + 1] = hp23;
                pla[j][o] = lp01; pla[j][o + 1] = lp23;
            }
#pragma unroll
            for (int j = 0; j < 2; j++) {
#pragma unroll
                for (int hnt = 0; hnt < 4; hnt++) {
                    u32 b0, b1, b2, b3;
                    ldsm4(b0, b1, b2, b3,
                          vlb + (u32)((hnt * 8 * VSTR + ch * 32 + j * 16) * 2));
                    u32 bvh[2] = { b0, b1 }, bvl[2] = { b2, b3 };
                    mma_bf16(oacc[hnt], pha[j], bvh);
                    mma_bf16(oacc[hnt], pla[j], bvh);
                    mma_bf16(oacc[hnt], pha[j], bvl);
                }
            }
        }
    }

    den1 += __shfl_xor_sync(0xffffffffu, den1, 1);
    den1 += __shfl_xor_sync(0xffffffffu, den1, 2);
    den2 += __shfl_xor_sync(0xffffffffu, den2, 1);
    den2 += __shfl_xor_sync(0xffffffffu, den2, 2);

    size_t r1g = (size_t)b * TT + trow1;
    size_t r2g = (size_t)b * TT + trow2;
    float* pa = g_pacc + ((size_t)slot * NROWS + r1g) * HS;
    float* pb = g_pacc + ((size_t)slot * NROWS + r2g) * HS;
#pragma unroll
    for (int hnt = 0; hnt < 4; hnt++) {
        int col = hnt * 8 + qc;
        *(float2*)(pa + col) = make_float2(oacc[hnt][0], oacc[hnt][1]);
        *(float2*)(pb + col) = make_float2(oacc[hnt][2], oacc[hnt][3]);
    }
    if ((lane & 3) == 0) {
        g_pden[slot * NROWS + r1g] = den1;
        g_pden[slot * NROWS + r2g] = den2;
    }
}

// -------------------------------------------------------------------------
// Combine: all 4 chunk slots unrolled + predicated so loads issue with
// MLP=8 instead of a serial dependent chain.
// -------------------------------------------------------------------------
__global__ void combine_kernel(float* __restrict__ out) {
    int gid = blockIdx.x * 256 + threadIdx.x;
    int row = gid >> 3;
    int q = gid & 7;
    int t = row & (TT - 1);
    int cmax = (t >> 7) >> 2;
    const float4* pacc4 = (const float4*)g_pacc;
    float den[4];
    float4 v[4];
#pragma unroll
    for (int c = 0; c < 4; c++) {
        bool on = (c <= cmax);
        den[c] = on ? g_pden[c * NROWS + row] : 0.f;
        v[c] = on ? pacc4[((size_t)c * NROWS + row) * 8 + q]
                  : make_float4(0.f, 0.f, 0.f, 0.f);
    }
    float dtot = (den[0] + den[1]) + (den[2] + den[3]);
    float4 a;
    a.x = (v[0].x + v[1].x) + (v[2].x + v[3].x);
    a.y = (v[0].y + v[1].y) + (v[2].y + v[3].y);
    a.z = (v[0].z + v[1].z) + (v[2].z + v[3].z);
    a.w = (v[0].w + v[1].w) + (v[2].w + v[3].w);
    float rinv = 1.f / dtot;
    ((float4*)out)[(size_t)row * 8 + q] =
        make_float4(a.x * rinv, a.y * rinv, a.z * rinv, a.w * rinv);
}

extern "C" void kernel_launch(void* const* d_in, const int* in_sizes, int n_in,
                              void* d_out, int out_size) {
    const float* x  = (const float*)d_in[0];
    const float* Wk = (const float*)d_in[1];
    const float* Wq = (const float*)d_in[2];
    const float* Wv = (const float*)d_in[3];
    float* out = (float*)d_out;

    prepack_kernel<<<(3 * NKS * 32 * 4 + 255) / 256, 256>>>(Wk, Wq, Wv);

    cudaFuncSetAttribute(proj_mma, cudaFuncAttributeMaxDynamicSharedMemorySize, PSM);
    proj_mma<<<NROWS / 64, 256, PSM>>>(x);

    cudaFuncSetAttribute(attn_mma, cudaFuncAttributeMaxDynamicSharedMemorySize, SMEMB);
    dim3 ag(40, BB);
    attn_mma<<<ag, 256, SMEMB>>>();

    combine_kernel<<<NROWS * 8 / 256, 256>>>(out);
}

// round 12
// speedup vs baseline: 2.8084x; 1.1515x over previous
#include <cuda_runtime.h>
#include <cuda_bf16.h>

#define BB 16
#define TT 2048
#define CC 288
#define HS 32
#define NROWS (BB*TT)
#define NKS (CC/16)
#define QKSCALE 0.17677669529663687f

typedef unsigned long long u64;
typedef unsigned int u32;

// ---- scratch (device globals; cudaMalloc forbidden) ----
__device__ __align__(16) __nv_bfloat16 g_kspl[NROWS*64];
__device__ __align__(16) __nv_bfloat16 g_qspl[NROWS*64];
__device__ __align__(16) __nv_bfloat16 g_vth[BB*HS*TT];
__device__ __align__(16) __nv_bfloat16 g_vtl[BB*HS*TT];
__device__ u64 g_wbh[3*NKS*32*4];
__device__ u64 g_wbl[3*NKS*32*4];
__device__ float g_pacc[(size_t)4*NROWS*HS];   // split-s partial P.V
__device__ float g_pden[4*NROWS];              // split-s partial sum(exp)

__device__ __forceinline__ u32 packbf(__nv_bfloat16 a, __nv_bfloat16 b) {
    return ((u32)__bfloat16_as_ushort(b) << 16) | (u32)__bfloat16_as_ushort(a);
}
__device__ __forceinline__ u32 smem_u32(const void* p) {
    u32 a; asm("{ .reg .u64 t; cvta.to.shared.u64 t, %1; cvt.u32.u64 %0, t; }" : "=r"(a) : "l"(p));
    return a;
}
__device__ __forceinline__ u32 cvt2bf(float hi, float lo) {
    u32 r; asm("cvt.rn.bf16x2.f32 %0,%1,%2;" : "=r"(r) : "f"(hi), "f"(lo)); return r;
}
__device__ __forceinline__ void mma_bf16(float* d, const u32* a, const u32* b) {
    asm volatile(
        "mma.sync.aligned.m16n8k16.row.col.f32.bf16.bf16.f32 "
        "{%0,%1,%2,%3}, {%4,%5,%6,%7}, {%8,%9}, {%0,%1,%2,%3};"
        : "+f"(d[0]), "+f"(d[1]), "+f"(d[2]), "+f"(d[3])
        : "r"(a[0]), "r"(a[1]), "r"(a[2]), "r"(a[3]), "r"(b[0]), "r"(b[1]));
}
__device__ __forceinline__ void ldsm4(u32& r0, u32& r1, u32& r2, u32& r3, u32 addr) {
    asm volatile("ldmatrix.sync.aligned.m8n8.x4.shared.b16 {%0,%1,%2,%3}, [%4];"
                 : "=r"(r0), "=r"(r1), "=r"(r2), "=r"(r3) : "r"(addr));
}
__device__ __forceinline__ void cpa16(u32 dst, const void* src) {
    asm volatile("cp.async.cg.shared.global [%0], [%1], 16;" :: "r"(dst), "l"(src));
}
#define CPCOMMIT() asm volatile("cp.async.commit_group;" ::: "memory")
#define CPWAIT0()  asm volatile("cp.async.wait_group 0;" ::: "memory")

// ---- (tile, chunk<<8) worklist: heavy chunks (4 s-tiles) first ----
static __device__ const int g_pairs[40] = {
    15, 15|256, 15|512, 15|768,
    14, 14|256, 14|512,
    13, 13|256, 13|512,
    12, 12|256, 12|512,
    11, 11|256, 11|512,
    10, 10|256, 9, 9|256, 8, 8|256, 7, 7|256,
    6, 5, 4, 3,
    14|768, 10|512, 6|256, 2,
    13|768, 9|512, 5|256, 1,
    12|768, 8|512, 4|256, 0
};

// -------------------------------------------------------------------------
// Prepack: W -> bf16 hi/lo B-fragment u64s, QKSCALE folded into Wk.
// -------------------------------------------------------------------------
__global__ void prepack_kernel(const float* __restrict__ Wk,
                               const float* __restrict__ Wq,
                               const float* __restrict__ Wv) {
    int i = blockIdx.x * 256 + threadIdx.x;
    if (i >= 3 * NKS * 32 * 4) return;
    int tig = i & 3;
    int n = (i >> 2) & 31;
    int ks = (i >> 7) % NKS;
    int p = i / (NKS * 32 * 4);
    const float* W = (p == 0) ? Wk : (p == 1) ? Wq : Wv;
    float s = (p == 0) ? QKSCALE : 1.0f;
    int c0 = ks * 16 + tig * 2;
    float w[4];
    w[0] = W[(c0)     * HS + n] * s;
    w[1] = W[(c0 + 1) * HS + n] * s;
    w[2] = W[(c0 + 8) * HS + n] * s;
    w[3] = W[(c0 + 9) * HS + n] * s;
    __nv_bfloat16 h[4]; float l[4];
#pragma unroll
    for (int j = 0; j < 4; j++) { h[j] = __float2bfloat16(w[j]); l[j] = w[j] - __bfloat162float(h[j]); }
    g_wbh[i] = ((u64)packbf(h[2], h[3]) << 32) | (u64)packbf(h[0], h[1]);
    g_wbl[i] = ((u64)packbf(__float2bfloat16(l[2]), __float2bfloat16(l[3])) << 32)
             | (u64)packbf(__float2bfloat16(l[0]), __float2bfloat16(l[1]));
}

// -------------------------------------------------------------------------
// Tensor-core projection. V staging aliased onto the (dead after MMA loop)
// x region -> 74 KB smem -> 3 CTAs/SM. W loads direct (L1-resident).
// -------------------------------------------------------------------------
#define XSTR 296
#define PSM (64*XSTR*2*2)

__global__ void __launch_bounds__(256, 3) proj_mma(const float* __restrict__ x) {
    extern __shared__ __nv_bfloat16 psm[];
    __nv_bfloat16* xhi = psm;
    __nv_bfloat16* vsh = psm;            // aliases x region (dead after MMA loop)
    __nv_bfloat16* vsl = psm + 2048;

    int tid = threadIdx.x;
    int row0 = blockIdx.x * 64;

    {
        const float4* xg = (const float4*)(x + (size_t)row0 * CC);
        for (int i = tid; i < 64 * 72; i += 256) {
            int row = i / 72, c4 = i % 72;
            float4 v = xg[i];
            __nv_bfloat16 h0 = __float2bfloat16(v.x), h1 = __float2bfloat16(v.y);
            __nv_bfloat16 h2 = __float2bfloat16(v.z), h3 = __float2bfloat16(v.w);
            *(uint2*)(xhi + row * XSTR + c4 * 4) =
                make_uint2(packbf(h0, h1), packbf(h2, h3));
            *(uint2*)(xhi + (64 + row) * XSTR + c4 * 4) = make_uint2(
                packbf(__float2bfloat16(v.x - __bfloat162float(h0)),
                       __float2bfloat16(v.y - __bfloat162float(h1))),
                packbf(__float2bfloat16(v.z - __bfloat162float(h2)),
                       __float2bfloat16(v.w - __bfloat162float(h3))));
        }
    }
    __syncthreads();

    int wid = tid >> 5, lane = tid & 31;
    int g = lane >> 2, tig = lane & 3;
    int rs = wid & 3, half = wid >> 2;
    int lr = lane & 7, lm = lane >> 3;

    u32 smb = smem_u32(psm);
    u32 xh_b = smb + (u32)(((rs * 16 + lr + (lm & 1) * 8) * XSTR + (lm >> 1) * 8) * 2);
    u32 xl_b = xh_b + (u32)(64 * XSTR * 2);

    int ou[6];
#pragma unroll
    for (int u = 0; u < 6; u++) {
        int idx = half * 6 + u;
        int p = idx >> 2, nt = idx & 3;
        ou[u] = ((p * NKS) * 32 + nt * 8 + g) * 4 + tig;
    }

    float oacc[6][4];
#pragma unroll
    for (int u = 0; u < 6; u++)
#pragma unroll
        for (int j = 0; j < 4; j++) oacc[u][j] = 0.f;

    for (int ks = 0; ks < NKS; ks++) {
        u32 ah[4], al[4];
        ldsm4(ah[0], ah[1], ah[2], ah[3], xh_b + (u32)(ks * 32));
        ldsm4(al[0], al[1], al[2], al[3], xl_b + (u32)(ks * 32));
        int o2 = ks * 128;
#pragma unroll
        for (int u = 0; u < 6; u++) {
            u64 wh = g_wbh[ou[u] + o2];
            u64 wl = g_wbl[ou[u] + o2];
            u32 bh[2] = { (u32)wh, (u32)(wh >> 32) };
            u32 bl[2] = { (u32)wl, (u32)(wl >> 32) };
            mma_bf16(oacc[u], ah, bh);
            mma_bf16(oacc[u], al, bh);
            mma_bf16(oacc[u], ah, bl);
        }
    }
    __syncthreads();   // x region dead; vsh/vsl alias it below

#pragma unroll
    for (int u = 0; u < 6; u++) {
        int idx = half * 6 + u;
        int p = idx >> 2, nt = idx & 3;
        int c0 = nt * 8 + 2 * tig;
        int rloc0 = rs * 16 + g;
#pragma unroll
        for (int rr = 0; rr < 2; rr++) {
            int rloc = rloc0 + rr * 8;
            float v0 = oacc[u][rr * 2], v1 = oacc[u][rr * 2 + 1];
            __nv_bfloat16 h0 = __float2bfloat16(v0), h1 = __float2bfloat16(v1);
            u32 hp = packbf(h0, h1);
            u32 lp = packbf(__float2bfloat16(v0 - __bfloat162float(h0)),
                            __float2bfloat16(v1 - __bfloat162float(h1)));
            if (p == 0) {
                size_t r = (size_t)(row0 + rloc) * 64;
                *(u32*)(g_kspl + r + c0) = hp;
                *(u32*)(g_kspl + r + 32 + c0) = lp;
            } else if (p == 1) {
                size_t r = (size_t)(row0 + rloc) * 64;
                *(u32*)(g_qspl + r + c0) = hp;
                *(u32*)(g_qspl + r + 32 + c0) = lp;
            } else {
                vsh[c0 * 64 + rloc] = h0;
                vsh[(c0 + 1) * 64 + rloc] = h1;
                vsl[c0 * 64 + rloc] = __ushort_as_bfloat16((unsigned short)(lp & 0xffff));
                vsl[(c0 + 1) * 64 + rloc] = __ushort_as_bfloat16((unsigned short)(lp >> 16));
            }
        }
    }
    __syncthreads();
    {
        int b = row0 >> 11, tin = row0 & (TT - 1);
        int h = tid >> 3, seg = tid & 7;
        size_t gb = ((size_t)(b * HS + h)) * TT + tin + seg * 8;
        *(uint4*)(g_vth + gb) = *(const uint4*)(vsh + h * 64 + seg * 8);
        *(uint4*)(g_vtl + gb) = *(const uint4*)(vsl + h * 64 + seg * 8);
    }
}

// -------------------------------------------------------------------------
// Flash attention, split-s + cp.async double buffering. Q buffer 1 aliases
// the K region (dead after K fragments move to registers) -> 70 KB smem ->
// 3 CTAs/SM.
// smem (elems): [K / Q1: 9216][Q0: 9216][V0: 8704][V1: 8704]
// -------------------------------------------------------------------------
#define KSTR 72
#define VSTR 136
#define QOFS0 9216
#define QOFS1 0
#define VB0   18432
#define VBSZ  8704
#define SMEMB (35840 * 2)

__device__ __forceinline__ void load_tile_async(u32 smb, int buf, int b, int s0, int tid) {
    const uint4* qg = (const uint4*)(g_qspl + ((size_t)(b * TT + s0)) * 64);
    u32 qb = smb + (buf ? (u32)(QOFS1 * 2) : (u32)(QOFS0 * 2));
#pragma unroll
    for (int k = 0; k < 4; k++) {
        int i = tid + k * 256;
        int row = i >> 3, seg = i & 7;
        cpa16(qb + (u32)((row * KSTR + seg * 8) * 2), qg + i);
    }
    u32 vhb = smb + (u32)((VB0 + buf * VBSZ) * 2);
    u32 vlb = vhb + (u32)(4352 * 2);
#pragma unroll
    for (int k = 0; k < 2; k++) {
        int i = tid + k * 256;
        int row = i >> 4, seg = i & 15;
        size_t base = ((size_t)(b * HS + row)) * TT + s0;
        u32 off = (u32)((row * VSTR + seg * 8) * 2);
        cpa16(vhb + off, ((const uint4*)(g_vth + base)) + seg);
        cpa16(vlb + off, ((const uint4*)(g_vtl + base)) + seg);
    }
}

__global__ void __launch_bounds__(256, 3) attn_mma() {
    extern __shared__ __nv_bfloat16 sm[];
    __nv_bfloat16* ks = sm;        // K region; becomes Q buffer 1

    int pr = g_pairs[blockIdx.x];
    int tile = pr & 0xff;
    int slot = pr >> 8;
    int b = blockIdx.y;

    int tid = threadIdx.x, wid = tid >> 5, lane = tid & 31;
    int qr = lane >> 2, qc = (lane & 3) << 1;
    int lr = lane & 7, lm = lane >> 3;
    int t0 = tile << 7;
    int r1 = (wid << 4) + qr;
    int trow1 = t0 + r1, trow2 = trow1 + 8;

    u32 smb = smem_u32(sm);
    u32 qcol2 = (lm == 0) ? 0u : (lm == 1) ? 16u : (lm == 2) ? 64u : 80u;
    u32 qlb_off = (u32)(lr * KSTR * 2) + qcol2;
    u32 vlb_off = ((lm & 2) ? (u32)(4352 * 2) : 0u) + (u32)(lr * VSTR * 2) + (u32)((lm & 1) * 16);

    int st_beg = slot * 4;
    int st_end = st_beg + 4;
    if (st_end > tile + 1) st_end = tile + 1;
    int nst = st_end - st_beg;

    // ---- K tile + first Q/V tile async ----
    {
        const uint4* kg = (const uint4*)(g_kspl + ((size_t)(b * TT + t0)) * 64);
        for (int i = tid; i < 1024; i += 256) {
            int row = i >> 3, seg = i & 7;
            *(uint4*)(ks + row * KSTR + seg * 8) = kg[row * 8 + seg];
        }
    }
    load_tile_async(smb, 0, b, st_beg << 7, tid);
    CPCOMMIT();
    __syncthreads();

    u32 aK[2][2][4];
#pragma unroll
    for (int sp = 0; sp < 2; sp++)
#pragma unroll
        for (int kk = 0; kk < 2; kk++) {
            int c = sp * 32 + kk * 16 + qc;
            aK[sp][kk][0] = *(const u32*)(ks + r1 * KSTR + c);
            aK[sp][kk][1] = *(const u32*)(ks + (r1 + 8) * KSTR + c);
            aK[sp][kk][2] = *(const u32*)(ks + r1 * KSTR + c + 8);
            aK[sp][kk][3] = *(const u32*)(ks + (r1 + 8) * KSTR + c + 8);
        }

    float oacc[4][4];
#pragma unroll
    for (int i = 0; i < 4; i++)
#pragma unroll
        for (int j = 0; j < 4; j++) oacc[i][j] = 0.f;
    float den1 = 0.f, den2 = 0.f;

    for (int it = 0; it < nst; it++) {
        int st = st_beg + it;
        int cur = it & 1;
        CPWAIT0();
        __syncthreads();   // all warps past aK loads / prior tile reads
        if (it + 1 < nst) {
            load_tile_async(smb, cur ^ 1, b, (st + 1) << 7, tid);
            CPCOMMIT();
        }
        u32 qlb = smb + (cur ? (u32)(QOFS1 * 2) : (u32)(QOFS0 * 2)) + qlb_off;
        u32 vlb = smb + (u32)((VB0 + cur * VBSZ) * 2) + vlb_off;

        bool diag = (st == tile);
#pragma unroll 1
        for (int ch = 0; ch < 4; ch++) {
            float sacc[4][4];
#pragma unroll
            for (int i = 0; i < 4; i++)
#pragma unroll
                for (int j = 0; j < 4; j++) sacc[i][j] = 0.f;
#pragma unroll
            for (int kk = 0; kk < 2; kk++) {
#pragma unroll
                for (int nt = 0; nt < 4; nt++) {
                    u32 b0, b1, b2, b3;
                    ldsm4(b0, b1, b2, b3,
                          qlb + (u32)((((ch * 32 + nt * 8) * KSTR) + kk * 16) * 2));
                    u32 bh[2] = { b0, b1 }, bl[2] = { b2, b3 };
                    mma_bf16(sacc[nt], aK[0][kk], bh);
                    mma_bf16(sacc[nt], aK[1][kk], bh);
                    mma_bf16(sacc[nt], aK[0][kk], bl);
                }
            }
            u32 pha[2][4], pla[2][4];
            int scb = (st << 7) + ch * 32;
#pragma unroll
            for (int nt = 0; nt < 4; nt++) {
                int c0 = scb + nt * 8 + qc;
                float p0, p1, p2, p3;
                if (diag) {
                    p0 = (c0     <= trow1) ? __expf(sacc[nt][0]) : 0.f;
                    p1 = (c0 + 1 <= trow1) ? __expf(sacc[nt][1]) : 0.f;
                    p2 = (c0     <= trow2) ? __expf(sacc[nt][2]) : 0.f;
                    p3 = (c0 + 1 <= trow2) ? __expf(sacc[nt][3]) : 0.f;
                } else {
                    p0 = __expf(sacc[nt][0]);
                    p1 = __expf(sacc[nt][1]);
                    p2 = __expf(sacc[nt][2]);
                    p3 = __expf(sacc[nt][3]);
                }
                den1 += p0 + p1;
                den2 += p2 + p3;
                u32 hp01 = cvt2bf(p1, p0);
                u32 hp23 = cvt2bf(p3, p2);
                float h0 = __uint_as_float(hp01 << 16);
                float h1 = __uint_as_float(hp01 & 0xffff0000u);
                float h2 = __uint_as_float(hp23 << 16);
                float h3 = __uint_as_float(hp23 & 0xffff0000u);
                u32 lp01 = cvt2bf(p1 - h1, p0 - h0);
                u32 lp23 = cvt2bf(p3 - h3, p2 - h2);
                int j = nt >> 1, o = (nt & 1) << 1;
                pha[j][o] = hp01; pha[j][o + 1] = hp23;
                pla[j][o] = lp01; pla[j][o + 1] = lp23;
            }
#pragma unroll
            for (int j = 0; j < 2; j++) {
#pragma unroll
                for (int hnt = 0; hnt < 4; hnt++) {
                    u32 b0, b1, b2, b3;
                    ldsm4(b0, b1, b2, b3,
                          vlb + (u32)((hnt * 8 * VSTR + ch * 32 + j * 16) * 2));
                    u32 bvh[2] = { b0, b1 }, bvl[2] = { b2, b3 };
                    mma_bf16(oacc[hnt], pha[j], bvh);
                    mma_bf16(oacc[hnt], pla[j], bvh);
                    mma_bf16(oacc[hnt], pha[j], bvl);
                }
            }
        }
    }

    den1 += __shfl_xor_sync(0xffffffffu, den1, 1);
    den1 += __shfl_xor_sync(0xffffffffu, den1, 2);
    den2 += __shfl_xor_sync(0xffffffffu, den2, 1);
    den2 += __shfl_xor_sync(0xffffffffu, den2, 2);

    size_t r1g = (size_t)b * TT + trow1;
    size_t r2g = (size_t)b * TT + trow2;
    float* pa = g_pacc + ((size_t)slot * NROWS + r1g) * HS;
    float* pb = g_pacc + ((size_t)slot * NROWS + r2g) * HS;
#pragma unroll
    for (int hnt = 0; hnt < 4; hnt++) {
        int col = hnt * 8 + qc;
        *(float2*)(pa + col) = make_float2(oacc[hnt][0], oacc[hnt][1]);
        *(float2*)(pb + col) = make_float2(oacc[hnt][2], oacc[hnt][3]);
    }
    if ((lane & 3) == 0) {
        g_pden[slot * NROWS + r1g] = den1;
        g_pden[slot * NROWS + r2g] = den2;
    }
}

// -------------------------------------------------------------------------
// Combine: all 4 chunk slots unrolled + predicated (MLP=8).
// -------------------------------------------------------------------------
__global__ void combine_kernel(float* __restrict__ out) {
    int gid = blockIdx.x * 256 + threadIdx.x;
    int row = gid >> 3;
    int q = gid & 7;
    int t = row & (TT - 1);
    int cmax = (t >> 7) >> 2;
    const float4* pacc4 = (const float4*)g_pacc;
    float den[4];
    float4 v[4];
#pragma unroll
    for (int c = 0; c < 4; c++) {
        bool on = (c <= cmax);
        den[c] = on ? g_pden[c * NROWS + row] : 0.f;
        v[c] = on ? pacc4[((size_t)c * NROWS + row) * 8 + q]
                  : make_float4(0.f, 0.f, 0.f, 0.f);
    }
    float dtot = (den[0] + den[1]) + (den[2] + den[3]);
    float4 a;
    a.x = (v[0].x + v[1].x) + (v[2].x + v[3].x);
    a.y = (v[0].y + v[1].y) + (v[2].y + v[3].y);
    a.z = (v[0].z + v[1].z) + (v[2].z + v[3].z);
    a.w = (v[0].w + v[1].w) + (v[2].w + v[3].w);
    float rinv = 1.f / dtot;
    ((float4*)out)[(size_t)row * 8 + q] =
        make_float4(a.x * rinv, a.y * rinv, a.z * rinv, a.w * rinv);
}

extern "C" void kernel_launch(void* const* d_in, const int* in_sizes, int n_in,
                              void* d_out, int out_size) {
    const float* x  = (const float*)d_in[0];
    const float* Wk = (const float*)d_in[1];
    const float* Wq = (const float*)d_in[2];
    const float* Wv = (const float*)d_in[3];
    float* out = (float*)d_out;

    prepack_kernel<<<(3 * NKS * 32 * 4 + 255) / 256, 256>>>(Wk, Wq, Wv);

    cudaFuncSetAttribute(proj_mma, cudaFuncAttributeMaxDynamicSharedMemorySize, PSM);
    proj_mma<<<NROWS / 64, 256, PSM>>>(x);

    cudaFuncSetAttribute(attn_mma, cudaFuncAttributeMaxDynamicSharedMemorySize, SMEMB);
    dim3 ag(40, BB);
    attn_mma<<<ag, 256, SMEMB>>>();

    combine_kernel<<<NROWS * 8 / 256, 256>>>(out);
}